// round 2
// baseline (speedup 1.0000x reference)
#include <cuda_runtime.h>
#include <math.h>

#define NN 50000
#define EE 800000
#define DD 128
#define BN_EPS 1e-5f

// ---------------- scratch (no allocs allowed) ----------------
__device__ float g_bufA[NN * DD];
__device__ float g_bufB[NN * DD];
__device__ float g_bufT[NN * DD];
__device__ float g_dis[NN];
__device__ float g_stats[2 * DD];

// ---------------- degree / norm ----------------
__global__ void k_deg_init() {
    int i = blockIdx.x * blockDim.x + threadIdx.x;
    if (i < NN) g_dis[i] = 1.0f;  // self-loop
}

__global__ void k_deg_edges(const int* __restrict__ ei) {
    int e = blockIdx.x * blockDim.x + threadIdx.x;
    if (e < EE) atomicAdd(&g_dis[ei[EE + e]], 1.0f);
}

__global__ void k_deg_fin() {
    int i = blockIdx.x * blockDim.x + threadIdx.x;
    if (i < NN) g_dis[i] = rsqrtf(g_dis[i]);
}

// ---------------- GEMM: C[n,128] = A[n,128] @ W[128,128] (+bias,relu) ----------------
// 256 threads, block tile 128x128, K=128 staged fully in smem, 8x8 microtile.
extern __shared__ float s_mem[];
__global__ void k_gemm(const float* __restrict__ A, const float* __restrict__ W,
                       const float* __restrict__ bias, float* __restrict__ C,
                       int n, int fuse_bias_relu) {
    float* sA = s_mem;              // 128*128
    float* sB = s_mem + 128 * 128;  // 128*128
    int t = threadIdx.x;
    int row0 = blockIdx.x * 128;

#pragma unroll
    for (int i = 0; i < 16; i++) {
        int idx = i * 256 + t;      // float4 index in [0,4096)
        int r = idx >> 5;
        int gr = row0 + r;
        float4 v = (gr < n) ? ((const float4*)A)[(size_t)gr * 32 + (idx & 31)]
                            : make_float4(0.f, 0.f, 0.f, 0.f);
        ((float4*)sA)[idx] = v;
        ((float4*)sB)[idx] = ((const float4*)W)[idx];
    }
    __syncthreads();

    int tx = t & 15, ty = t >> 4;
    int r0 = ty * 8, c0 = tx * 8;
    float acc[8][8];
#pragma unroll
    for (int i = 0; i < 8; i++)
#pragma unroll
        for (int j = 0; j < 8; j++) acc[i][j] = 0.f;

    for (int k = 0; k < 128; k += 4) {
        float4 a4[8];
#pragma unroll
        for (int i = 0; i < 8; i++)
            a4[i] = *(const float4*)&sA[(r0 + i) * 128 + k];
#pragma unroll
        for (int kk = 0; kk < 4; kk++) {
            float4 b0 = *(const float4*)&sB[(k + kk) * 128 + c0];
            float4 b1 = *(const float4*)&sB[(k + kk) * 128 + c0 + 4];
            float bb[8] = {b0.x, b0.y, b0.z, b0.w, b1.x, b1.y, b1.z, b1.w};
#pragma unroll
            for (int i = 0; i < 8; i++) {
                float av = ((const float*)&a4[i])[kk];
#pragma unroll
                for (int j = 0; j < 8; j++) acc[i][j] += av * bb[j];
            }
        }
    }

    float bv[8];
    if (fuse_bias_relu) {
        float4 q0 = ((const float4*)bias)[c0 >> 2];
        float4 q1 = ((const float4*)bias)[(c0 >> 2) + 1];
        bv[0] = q0.x; bv[1] = q0.y; bv[2] = q0.z; bv[3] = q0.w;
        bv[4] = q1.x; bv[5] = q1.y; bv[6] = q1.z; bv[7] = q1.w;
    }
#pragma unroll
    for (int i = 0; i < 8; i++) {
        int gr = row0 + r0 + i;
        if (gr < n) {
            float o[8];
#pragma unroll
            for (int j = 0; j < 8; j++) {
                float v = acc[i][j];
                if (fuse_bias_relu) v = fmaxf(v + bv[j], 0.f);
                o[j] = v;
            }
            ((float4*)C)[(size_t)gr * 32 + (c0 >> 2)]     = make_float4(o[0], o[1], o[2], o[3]);
            ((float4*)C)[(size_t)gr * 32 + (c0 >> 2) + 1] = make_float4(o[4], o[5], o[6], o[7]);
        }
    }
}

// ---------------- scatter: self-loop + bias init, then edge RED ----------------
__global__ void k_scatter_init(const float* __restrict__ T, const float* __restrict__ bias,
                               float* __restrict__ O) {
    int idx = blockIdx.x * blockDim.x + threadIdx.x;  // float4 index
    if (idx < NN * 32) {
        int i = idx >> 5;
        float d = g_dis[i];
        float s = d * d;
        float4 v = ((const float4*)T)[idx];
        float4 b = ((const float4*)bias)[idx & 31];
        ((float4*)O)[idx] = make_float4(b.x + v.x * s, b.y + v.y * s,
                                        b.z + v.z * s, b.w + v.w * s);
    }
}

__device__ __forceinline__ void red_add_f4(float4* p, float4 v) {
    asm volatile("red.global.add.v4.f32 [%0], {%1, %2, %3, %4};"
                 :: "l"(p), "f"(v.x), "f"(v.y), "f"(v.z), "f"(v.w)
                 : "memory");
}

__global__ void k_scatter_edges(const float* __restrict__ T, const int* __restrict__ ei,
                                float* __restrict__ O) {
    int lane = threadIdx.x & 31;
    int warp = (blockIdx.x * blockDim.x + threadIdx.x) >> 5;
    int nwarps = (gridDim.x * blockDim.x) >> 5;
    for (int e = warp; e < EE; e += nwarps) {
        int src = ei[e];
        int dst = ei[EE + e];
        float nrm = g_dis[src] * g_dis[dst];
        float4 v = ((const float4*)T)[(size_t)src * 32 + lane];
        v.x *= nrm; v.y *= nrm; v.z *= nrm; v.w *= nrm;
        red_add_f4(((float4*)O) + (size_t)dst * 32 + lane, v);
    }
}

// ---------------- batchnorm ----------------
__global__ void k_zero_stats() {
    if (threadIdx.x < 2 * DD) g_stats[threadIdx.x] = 0.f;
}

__global__ void k_bn_stats(const float* __restrict__ H, int n, int relu_first) {
    int c = threadIdx.x & 127;
    int r0 = blockIdx.x * 4 + (threadIdx.x >> 7);  // blockDim = 512
    float s = 0.f, q = 0.f;
    for (int r = r0; r < n; r += gridDim.x * 4) {
        float v = H[(size_t)r * 128 + c];
        if (relu_first) v = fmaxf(v, 0.f);
        s += v;
        q += v * v;
    }
    atomicAdd(&g_stats[c], s);
    atomicAdd(&g_stats[128 + c], q);
}

// mode 0: y = relu(bn(v));  mode 1: y = bn(relu(v))
__global__ void k_bn_apply(const float* __restrict__ H, float* __restrict__ Y,
                           const float* __restrict__ gamma, const float* __restrict__ beta,
                           int n, int mode) {
    int idx = blockIdx.x * blockDim.x + threadIdx.x;  // float4 index
    if (idx >= NN * 32) return;
    int c4 = idx & 31;
    int c0 = c4 * 4;
    float inv = 1.0f / (float)n;
    float4 v  = ((const float4*)H)[idx];
    float4 su = *(const float4*)&g_stats[c0];
    float4 sq = *(const float4*)&g_stats[128 + c0];
    float4 g  = ((const float4*)gamma)[c4];
    float4 b  = ((const float4*)beta)[c4];
    float o[4];
    float vv[4] = {v.x, v.y, v.z, v.w};
    float ss[4] = {su.x, su.y, su.z, su.w};
    float qq[4] = {sq.x, sq.y, sq.z, sq.w};
    float gg[4] = {g.x, g.y, g.z, g.w};
    float bb[4] = {b.x, b.y, b.z, b.w};
#pragma unroll
    for (int j = 0; j < 4; j++) {
        float mean = ss[j] * inv;
        float var = qq[j] * inv - mean * mean;
        float rstd = rsqrtf(var + BN_EPS);
        float x = vv[j];
        if (mode == 1) x = fmaxf(x, 0.f);
        float y = (x - mean) * rstd * gg[j] + bb[j];
        if (mode == 0) y = fmaxf(y, 0.f);
        o[j] = y;
    }
    ((float4*)Y)[idx] = make_float4(o[0], o[1], o[2], o[3]);
}

// ---------------- output head: sigmoid(h @ w + b) ----------------
__global__ void k_out(const float* __restrict__ H, const float* __restrict__ w,
                      const float* __restrict__ b, float* __restrict__ out) {
    int warp = (blockIdx.x * blockDim.x + threadIdx.x) >> 5;
    int lane = threadIdx.x & 31;
    if (warp >= NN) return;
    float4 h = ((const float4*)H)[(size_t)warp * 32 + lane];
    float4 ww = ((const float4*)w)[lane];
    float s = h.x * ww.x + h.y * ww.y + h.z * ww.z + h.w * ww.w;
#pragma unroll
    for (int o = 16; o; o >>= 1) s += __shfl_down_sync(0xFFFFFFFFu, s, o);
    if (lane == 0) out[warp] = 1.0f / (1.0f + expf(-(s + b[0])));
}

// ---------------- launch ----------------
extern "C" void kernel_launch(void* const* d_in, const int* in_sizes, int n_in,
                              void* d_out, int out_size) {
    const float *x = nullptr, *conv_w = nullptr, *conv_b = nullptr;
    const float *bn_g = nullptr, *bn_b = nullptr, *mlp_w = nullptr, *mlp_b = nullptr;
    const float *out_w = nullptr, *out_b = nullptr;
    const int* ei = nullptr;
    int n256 = 0;
    for (int i = 0; i < n_in; i++) {
        switch (in_sizes[i]) {
            case 6400000: x = (const float*)d_in[i]; break;
            case 1600000: ei = (const int*)d_in[i]; break;
            case 49152:   conv_w = (const float*)d_in[i]; break;
            case 384:     conv_b = (const float*)d_in[i]; break;
            case 32768:   mlp_w = (const float*)d_in[i]; break;
            case 128:     out_w = (const float*)d_in[i]; break;
            case 1:       out_b = (const float*)d_in[i]; break;
            case 256:
                if (n256 == 0) bn_g = (const float*)d_in[i];
                else if (n256 == 1) bn_b = (const float*)d_in[i];
                else mlp_b = (const float*)d_in[i];
                n256++;
                break;
            default: break;
        }
    }

    float *bufA, *bufB, *bufT;
    cudaGetSymbolAddress((void**)&bufA, g_bufA);
    cudaGetSymbolAddress((void**)&bufB, g_bufB);
    cudaGetSymbolAddress((void**)&bufT, g_bufT);

    cudaFuncSetAttribute(k_gemm, cudaFuncAttributeMaxDynamicSharedMemorySize, 131072);

    // degree -> dis = deg^{-1/2}
    k_deg_init<<<(NN + 255) / 256, 256>>>();
    k_deg_edges<<<(EE + 255) / 256, 256>>>(ei);
    k_deg_fin<<<(NN + 255) / 256, 256>>>();

    const int GB = (NN + 127) / 128;      // 391 gemm blocks
    const int EL = (NN * 32 + 255) / 256; // elementwise float4 grid

    const float* h = x;
    for (int l = 0; l < 3; l++) {
        k_gemm<<<GB, 256, 131072>>>(h, conv_w + l * 128 * 128, nullptr, bufT, NN, 0);
        k_scatter_init<<<EL, 256>>>(bufT, conv_b + l * 128, bufB);
        k_scatter_edges<<<2048, 256>>>(bufT, ei, bufB);
        k_zero_stats<<<1, 256>>>();
        k_bn_stats<<<256, 512>>>(bufB, NN, (l == 2) ? 1 : 0);
        int gi = (l == 0) ? 0 : 128;  // layer2 reuses bn[1] (reference quirk)
        k_bn_apply<<<EL, 256>>>(bufB, bufA, bn_g + gi, bn_b + gi, NN, (l == 2) ? 1 : 0);
        h = bufA;
    }

    // MLP head
    k_gemm<<<GB, 256, 131072>>>(bufA, mlp_w, mlp_b, bufB, NN, 1);
    k_gemm<<<GB, 256, 131072>>>(bufB, mlp_w + 128 * 128, mlp_b + 128, bufA, NN, 1);
    k_out<<<(NN * 32 + 255) / 256, 256>>>(bufA, out_w, out_b, (float*)d_out);
}

// round 3
// speedup vs baseline: 1.2629x; 1.2629x over previous
#include <cuda_runtime.h>
#include <math.h>

#define NN 50000
#define EE 800000
#define DD 128
#define BN_EPS 1e-5f
#define SCAN_CHUNK 128
#define SCAN_NT ((NN + SCAN_CHUNK - 1) / SCAN_CHUNK)   // 391

// ---------------- scratch (no allocs allowed) ----------------
__device__ float g_bufA[NN * DD];
__device__ float g_bufB[NN * DD];
__device__ float g_bufT[NN * DD];
__device__ float g_dis[NN];
__device__ float g_stats[2 * DD];
__device__ int   g_cnt[NN];
__device__ int   g_rowptr[NN];
__device__ int   g_cursor[NN];
__device__ int   g_csrc[EE];
__device__ float g_cw[EE];
__device__ int   g_tsum[512];

// ---------------- CSR build ----------------
__global__ void k_zero_cnt() {
    int i = blockIdx.x * blockDim.x + threadIdx.x;
    if (i < NN) g_cnt[i] = 0;
}

__global__ void k_hist(const int* __restrict__ ei) {
    int e = blockIdx.x * blockDim.x + threadIdx.x;
    if (e < EE) atomicAdd(&g_cnt[ei[EE + e]], 1);
}

__global__ void k_deg() {
    int i = blockIdx.x * blockDim.x + threadIdx.x;
    if (i < NN) g_dis[i] = rsqrtf((float)g_cnt[i] + 1.0f);  // +1 self-loop
}

__global__ void k_scanA() {
    int t = blockIdx.x * blockDim.x + threadIdx.x;
    if (t >= 512) return;
    int s = 0;
    if (t < SCAN_NT) {
        int base = t * SCAN_CHUNK;
        int end = min(base + SCAN_CHUNK, NN);
        for (int i = base; i < end; i++) s += g_cnt[i];
    }
    g_tsum[t] = s;
}

__global__ void k_scanB() {
    __shared__ int s[512];
    int t = threadIdx.x;
    int v = g_tsum[t];
    s[t] = v;
    __syncthreads();
    for (int o = 1; o < 512; o <<= 1) {
        int x = (t >= o) ? s[t - o] : 0;
        __syncthreads();
        s[t] += x;
        __syncthreads();
    }
    g_tsum[t] = s[t] - v;  // exclusive
}

__global__ void k_scanC() {
    int t = blockIdx.x * blockDim.x + threadIdx.x;
    if (t >= SCAN_NT) return;
    int run = g_tsum[t];
    int base = t * SCAN_CHUNK;
    int end = min(base + SCAN_CHUNK, NN);
    for (int i = base; i < end; i++) {
        g_rowptr[i] = run;
        g_cursor[i] = run;
        run += g_cnt[i];
    }
}

__global__ void k_fill(const int* __restrict__ ei) {
    int e = blockIdx.x * blockDim.x + threadIdx.x;
    if (e >= EE) return;
    int src = ei[e];
    int dst = ei[EE + e];
    int pos = atomicAdd(&g_cursor[dst], 1);
    g_csrc[pos] = src;
    g_cw[pos] = g_dis[src] * g_dis[dst];
}

// ---------------- GEMM: C[n,128] = f(A)[n,128] @ W[128,128] ----------------
// tmode: 0 = identity, 1 = relu(bn(v))  [layers 0,1], 2 = bn(relu(v)) [layer 2 quirk]
// epi:   0 = raw, 1 = relu(. + bias)
extern __shared__ float s_mem[];
__global__ void k_gemm(const float* __restrict__ A, const float* __restrict__ W,
                       const float* __restrict__ bias, float* __restrict__ C,
                       int n, int epi, int tmode,
                       const float* __restrict__ gamma, const float* __restrict__ beta) {
    __shared__ float s_scale[128], s_shift[128];
    float* sA = s_mem;              // 128*128
    float* sB = s_mem + 128 * 128;  // 128*128
    int t = threadIdx.x;
    int row0 = blockIdx.x * 128;

    if (tmode && t < 128) {
        float inv = 1.0f / (float)NN;
        float mean = g_stats[t] * inv;
        float var = g_stats[128 + t] * inv - mean * mean;
        float rs = rsqrtf(var + BN_EPS);
        float sc = rs * gamma[t];
        s_scale[t] = sc;
        s_shift[t] = beta[t] - mean * sc;
    }
    __syncthreads();

#pragma unroll
    for (int i = 0; i < 16; i++) {
        int idx = i * 256 + t;  // float4 index in [0,4096)
        int r = idx >> 5;
        int gr = row0 + r;
        float4 v = (gr < n) ? ((const float4*)A)[(size_t)gr * 32 + (idx & 31)]
                            : make_float4(0.f, 0.f, 0.f, 0.f);
        if (tmode) {
            int c0 = (idx & 31) * 4;
            float vv[4] = {v.x, v.y, v.z, v.w};
#pragma unroll
            for (int j = 0; j < 4; j++) {
                float x = vv[j];
                if (tmode == 2) x = fmaxf(x, 0.f);
                float y = x * s_scale[c0 + j] + s_shift[c0 + j];
                if (tmode == 1) y = fmaxf(y, 0.f);
                vv[j] = y;
            }
            v = make_float4(vv[0], vv[1], vv[2], vv[3]);
        }
        ((float4*)sA)[idx] = v;
        ((float4*)sB)[idx] = ((const float4*)W)[idx];
    }
    __syncthreads();

    int tx = t & 15, ty = t >> 4;
    int r0 = ty * 8, c0 = tx * 8;
    float acc[8][8];
#pragma unroll
    for (int i = 0; i < 8; i++)
#pragma unroll
        for (int j = 0; j < 8; j++) acc[i][j] = 0.f;

    for (int k = 0; k < 128; k += 4) {
        float4 a4[8];
#pragma unroll
        for (int i = 0; i < 8; i++)
            a4[i] = *(const float4*)&sA[(r0 + i) * 128 + k];
#pragma unroll
        for (int kk = 0; kk < 4; kk++) {
            float4 b0 = *(const float4*)&sB[(k + kk) * 128 + c0];
            float4 b1 = *(const float4*)&sB[(k + kk) * 128 + c0 + 4];
            float bb[8] = {b0.x, b0.y, b0.z, b0.w, b1.x, b1.y, b1.z, b1.w};
#pragma unroll
            for (int i = 0; i < 8; i++) {
                float av = ((const float*)&a4[i])[kk];
#pragma unroll
                for (int j = 0; j < 8; j++) acc[i][j] += av * bb[j];
            }
        }
    }

    float bv[8];
    if (epi) {
        float4 q0 = ((const float4*)bias)[c0 >> 2];
        float4 q1 = ((const float4*)bias)[(c0 >> 2) + 1];
        bv[0] = q0.x; bv[1] = q0.y; bv[2] = q0.z; bv[3] = q0.w;
        bv[4] = q1.x; bv[5] = q1.y; bv[6] = q1.z; bv[7] = q1.w;
    }
#pragma unroll
    for (int i = 0; i < 8; i++) {
        int gr = row0 + r0 + i;
        if (gr < n) {
            float o[8];
#pragma unroll
            for (int j = 0; j < 8; j++) {
                float v = acc[i][j];
                if (epi) v = fmaxf(v + bv[j], 0.f);
                o[j] = v;
            }
            ((float4*)C)[(size_t)gr * 32 + (c0 >> 2)]     = make_float4(o[0], o[1], o[2], o[3]);
            ((float4*)C)[(size_t)gr * 32 + (c0 >> 2) + 1] = make_float4(o[4], o[5], o[6], o[7]);
        }
    }
}

// ---------------- CSR gather: O[n] = bias + dis[n]^2*T[n] + sum_e w_e*T[src_e] ----------------
// Also accumulates BN stats (sum, sumsq) over h (or relu(h) if relu_first).
__global__ void k_gather(const float* __restrict__ T, const float* __restrict__ bias,
                         float* __restrict__ O, int relu_first) {
    __shared__ float ss[8 * 128];
    __shared__ float sq[8 * 128];
    int t = threadIdx.x;
    int lane = t & 31, wid = t >> 5;
    int gw = blockIdx.x * 8 + wid;
    int tot = gridDim.x * 8;
    float4 b4 = ((const float4*)bias)[lane];
    float lsx = 0, lsy = 0, lsz = 0, lsw = 0;
    float lqx = 0, lqy = 0, lqz = 0, lqw = 0;

    for (int n = gw; n < NN; n += tot) {
        float dn = g_dis[n];
        float sn = dn * dn;
        float4 v = ((const float4*)T)[(size_t)n * 32 + lane];
        float ax = b4.x + sn * v.x;
        float ay = b4.y + sn * v.y;
        float az = b4.z + sn * v.z;
        float aw = b4.w + sn * v.w;
        int s = g_rowptr[n];
        int e = s + g_cnt[n];
        for (int i = s; i < e; i++) {
            int src = __ldg(&g_csrc[i]);
            float w = __ldg(&g_cw[i]);
            float4 u = ((const float4*)T)[(size_t)src * 32 + lane];
            ax += w * u.x; ay += w * u.y; az += w * u.z; aw += w * u.w;
        }
        ((float4*)O)[(size_t)n * 32 + lane] = make_float4(ax, ay, az, aw);
        float rx = ax, ry = ay, rz = az, rw = aw;
        if (relu_first) {
            rx = fmaxf(rx, 0.f); ry = fmaxf(ry, 0.f);
            rz = fmaxf(rz, 0.f); rw = fmaxf(rw, 0.f);
        }
        lsx += rx; lsy += ry; lsz += rz; lsw += rw;
        lqx += rx * rx; lqy += ry * ry; lqz += rz * rz; lqw += rw * rw;
    }
    // per-warp slice (no smem atomics)
    float* ps = &ss[wid * 128 + lane * 4];
    float* pq = &sq[wid * 128 + lane * 4];
    ps[0] = lsx; ps[1] = lsy; ps[2] = lsz; ps[3] = lsw;
    pq[0] = lqx; pq[1] = lqy; pq[2] = lqz; pq[3] = lqw;
    __syncthreads();
    if (t < 128) {
        float a = 0.f, b = 0.f;
#pragma unroll
        for (int w = 0; w < 8; w++) {
            a += ss[w * 128 + t];
            b += sq[w * 128 + t];
        }
        atomicAdd(&g_stats[t], a);
        atomicAdd(&g_stats[128 + t], b);
    }
}

__global__ void k_zero_stats() {
    if (threadIdx.x < 2 * DD) g_stats[threadIdx.x] = 0.f;
}

// ---------------- output head: sigmoid(h @ w + b) ----------------
__global__ void k_out(const float* __restrict__ H, const float* __restrict__ w,
                      const float* __restrict__ b, float* __restrict__ out) {
    int warp = (blockIdx.x * blockDim.x + threadIdx.x) >> 5;
    int lane = threadIdx.x & 31;
    if (warp >= NN) return;
    float4 h = ((const float4*)H)[(size_t)warp * 32 + lane];
    float4 ww = ((const float4*)w)[lane];
    float s = h.x * ww.x + h.y * ww.y + h.z * ww.z + h.w * ww.w;
#pragma unroll
    for (int o = 16; o; o >>= 1) s += __shfl_down_sync(0xFFFFFFFFu, s, o);
    if (lane == 0) out[warp] = 1.0f / (1.0f + expf(-(s + b[0])));
}

// ---------------- launch ----------------
extern "C" void kernel_launch(void* const* d_in, const int* in_sizes, int n_in,
                              void* d_out, int out_size) {
    const float *x = nullptr, *conv_w = nullptr, *conv_b = nullptr;
    const float *bn_g = nullptr, *bn_b = nullptr, *mlp_w = nullptr, *mlp_b = nullptr;
    const float *out_w = nullptr, *out_b = nullptr;
    const int* ei = nullptr;
    int n256 = 0;
    for (int i = 0; i < n_in; i++) {
        switch (in_sizes[i]) {
            case 6400000: x = (const float*)d_in[i]; break;
            case 1600000: ei = (const int*)d_in[i]; break;
            case 49152:   conv_w = (const float*)d_in[i]; break;
            case 384:     conv_b = (const float*)d_in[i]; break;
            case 32768:   mlp_w = (const float*)d_in[i]; break;
            case 128:     out_w = (const float*)d_in[i]; break;
            case 1:       out_b = (const float*)d_in[i]; break;
            case 256:
                if (n256 == 0) bn_g = (const float*)d_in[i];
                else if (n256 == 1) bn_b = (const float*)d_in[i];
                else mlp_b = (const float*)d_in[i];
                n256++;
                break;
            default: break;
        }
    }

    float *bufA, *bufB, *bufT;
    cudaGetSymbolAddress((void**)&bufA, g_bufA);
    cudaGetSymbolAddress((void**)&bufB, g_bufB);
    cudaGetSymbolAddress((void**)&bufT, g_bufT);

    cudaFuncSetAttribute(k_gemm, cudaFuncAttributeMaxDynamicSharedMemorySize, 131072);

    const int GB = (NN + 127) / 128;  // 391 gemm blocks
    const int NB = (NN + 255) / 256;  // 196
    const int EB = (EE + 255) / 256;  // 3125

    // CSR build (by dst) + degree norm
    k_zero_cnt<<<NB, 256>>>();
    k_hist<<<EB, 256>>>(ei);
    k_deg<<<NB, 256>>>();
    k_scanA<<<2, 256>>>();
    k_scanB<<<1, 512>>>();
    k_scanC<<<2, 256>>>();
    k_fill<<<EB, 256>>>(ei);

    // layer 0: gemm(x) -> gather (+stats0)
    k_zero_stats<<<1, 256>>>();
    k_gemm<<<GB, 256, 131072>>>(x, conv_w, nullptr, bufT, NN, 0, 0, nullptr, nullptr);
    k_gather<<<1184, 256>>>(bufT, conv_b, bufB, 0);

    // layer 1: gemm(relu(bn0(h0))) -> gather (+stats1)
    k_gemm<<<GB, 256, 131072>>>(bufB, conv_w + 1 * 128 * 128, nullptr, bufT, NN, 0, 1, bn_g, bn_b);
    k_zero_stats<<<1, 256>>>();
    k_gather<<<1184, 256>>>(bufT, conv_b + 128, bufB, 0);

    // layer 2: gemm(relu(bn1(h1))) -> gather (+stats over relu(h2))
    k_gemm<<<GB, 256, 131072>>>(bufB, conv_w + 2 * 128 * 128, nullptr, bufT, NN, 0, 1, bn_g + 128, bn_b + 128);
    k_zero_stats<<<1, 256>>>();
    k_gather<<<1184, 256>>>(bufT, conv_b + 256, bufB, 1);

    // mlp1: input = bn1(relu(h2))  (reference quirk: bns[-1] reused), epi = relu(.+b)
    k_gemm<<<GB, 256, 131072>>>(bufB, mlp_w, mlp_b, bufA, NN, 1, 2, bn_g + 128, bn_b + 128);
    // mlp2
    k_gemm<<<GB, 256, 131072>>>(bufA, mlp_w + 128 * 128, mlp_b + 128, bufB, NN, 1, 0, nullptr, nullptr);

    k_out<<<(NN * 32 + 255) / 256, 256>>>(bufB, out_w, out_b, (float*)d_out);
}

// round 4
// speedup vs baseline: 1.6148x; 1.2786x over previous
#include <cuda_runtime.h>
#include <math.h>

#define NN 50000
#define EE 800000
#define DD 128
#define BN_EPS 1e-5f
#define SCAN_CHUNK 128
#define SCAN_NT ((NN + SCAN_CHUNK - 1) / SCAN_CHUNK)   // 391

typedef unsigned long long u64;

// ---------------- scratch (no allocs allowed) ----------------
__device__ float g_bufA[NN * DD];
__device__ float g_bufB[NN * DD];
__device__ float g_bufT[NN * DD];
__device__ float g_dis[NN];
__device__ float g_stats[2 * DD];
__device__ int   g_cnt[NN];
__device__ int   g_rowptr[NN];
__device__ int   g_cursor[NN];
__device__ int   g_csrc[EE];
__device__ float g_cw[EE];
__device__ int   g_tsum[512];

// ---------------- packed f32x2 helpers ----------------
__device__ __forceinline__ u64 ffma2(u64 a, u64 b, u64 c) {
    u64 d;
    asm("fma.rn.f32x2 %0, %1, %2, %3;" : "=l"(d) : "l"(a), "l"(b), "l"(c));
    return d;
}
__device__ __forceinline__ u64 dup2(float x) {
    u64 d;
    asm("mov.b64 %0, {%1, %1};" : "=l"(d) : "f"(x));
    return d;
}
__device__ __forceinline__ u64 pack2(float lo, float hi) {
    u64 d;
    asm("mov.b64 %0, {%1, %2};" : "=l"(d) : "f"(lo), "f"(hi));
    return d;
}
__device__ __forceinline__ float2 unpack2(u64 v) {
    float2 f;
    asm("mov.b64 {%0, %1}, %2;" : "=f"(f.x), "=f"(f.y) : "l"(v));
    return f;
}

// ---------------- CSR build ----------------
__global__ void k_zero_cnt() {
    int i = blockIdx.x * blockDim.x + threadIdx.x;
    if (i < NN) g_cnt[i] = 0;
}

__global__ void k_hist(const int* __restrict__ ei) {
    int e = blockIdx.x * blockDim.x + threadIdx.x;
    if (e < EE) atomicAdd(&g_cnt[ei[EE + e]], 1);
}

__global__ void k_deg() {
    int i = blockIdx.x * blockDim.x + threadIdx.x;
    if (i < NN) g_dis[i] = rsqrtf((float)g_cnt[i] + 1.0f);  // +1 self-loop
}

// tile sums: grid SCAN_NT, block 128
__global__ void k_scanA() {
    __shared__ int sh[4];
    int t = threadIdx.x;
    int i = blockIdx.x * 128 + t;
    int v = (i < NN) ? g_cnt[i] : 0;
#pragma unroll
    for (int o = 16; o; o >>= 1) v += __shfl_down_sync(0xFFFFFFFFu, v, o);
    if ((t & 31) == 0) sh[t >> 5] = v;
    __syncthreads();
    if (t == 0) g_tsum[blockIdx.x] = sh[0] + sh[1] + sh[2] + sh[3];
}

// exclusive scan of 391 tile sums in one block
__global__ void k_scanB() {
    __shared__ int s[512];
    int t = threadIdx.x;
    int v = (t < SCAN_NT) ? g_tsum[t] : 0;
    s[t] = v;
    __syncthreads();
    for (int o = 1; o < 512; o <<= 1) {
        int x = (t >= o) ? s[t - o] : 0;
        __syncthreads();
        s[t] += x;
        __syncthreads();
    }
    if (t < SCAN_NT) g_tsum[t] = s[t] - v;  // exclusive
}

// per-tile scan + offset: grid SCAN_NT, block 128
__global__ void k_scanC() {
    __shared__ int sh[128];
    int t = threadIdx.x;
    int i = blockIdx.x * 128 + t;
    int v = (i < NN) ? g_cnt[i] : 0;
    sh[t] = v;
    __syncthreads();
    for (int o = 1; o < 128; o <<= 1) {
        int x = (t >= o) ? sh[t - o] : 0;
        __syncthreads();
        sh[t] += x;
        __syncthreads();
    }
    if (i < NN) {
        int ex = sh[t] - v + g_tsum[blockIdx.x];
        g_rowptr[i] = ex;
        g_cursor[i] = ex;
    }
}

__global__ void k_fill(const int* __restrict__ ei) {
    int e = blockIdx.x * blockDim.x + threadIdx.x;
    if (e >= EE) return;
    int src = ei[e];
    int dst = ei[EE + e];
    int pos = atomicAdd(&g_cursor[dst], 1);
    g_csrc[pos] = src;
    g_cw[pos] = g_dis[src] * g_dis[dst];
}

// ---------------- GEMM: C[n,128] = f(A)[n,128] @ W[128,128] ----------------
// tmode: 0 = identity, 1 = relu(bn(v)), 2 = bn(relu(v))
// epi:   0 = raw, 1 = relu(. + bias)
extern __shared__ float s_mem[];
__global__ void __launch_bounds__(256, 1)
k_gemm(const float* __restrict__ A, const float* __restrict__ W,
       const float* __restrict__ bias, float* __restrict__ C,
       int n, int epi, int tmode,
       const float* __restrict__ gamma, const float* __restrict__ beta) {
    __shared__ float s_scale[128], s_shift[128];
    float* sA = s_mem;              // 128*128
    float* sB = s_mem + 128 * 128;  // 128*128
    int t = threadIdx.x;
    int row0 = blockIdx.x * 128;

    if (tmode && t < 128) {
        float inv = 1.0f / (float)NN;
        float mean = g_stats[t] * inv;
        float var = g_stats[128 + t] * inv - mean * mean;
        float rs = rsqrtf(var + BN_EPS);
        float sc = rs * gamma[t];
        s_scale[t] = sc;
        s_shift[t] = beta[t] - mean * sc;
    }
    __syncthreads();

#pragma unroll
    for (int i = 0; i < 16; i++) {
        int idx = i * 256 + t;  // float4 index in [0,4096)
        int r = idx >> 5;
        int gr = row0 + r;
        float4 v = (gr < n) ? ((const float4*)A)[(size_t)gr * 32 + (idx & 31)]
                            : make_float4(0.f, 0.f, 0.f, 0.f);
        if (tmode) {
            int c0 = (idx & 31) * 4;
            float vv[4] = {v.x, v.y, v.z, v.w};
#pragma unroll
            for (int j = 0; j < 4; j++) {
                float x = vv[j];
                if (tmode == 2) x = fmaxf(x, 0.f);
                float y = x * s_scale[c0 + j] + s_shift[c0 + j];
                if (tmode == 1) y = fmaxf(y, 0.f);
                vv[j] = y;
            }
            v = make_float4(vv[0], vv[1], vv[2], vv[3]);
        }
        ((float4*)sA)[idx] = v;
        ((float4*)sB)[idx] = ((const float4*)W)[idx];
    }
    __syncthreads();

    int tx = t & 15, ty = t >> 4;
    int r0 = ty * 8, c0 = tx * 8;
    // accumulators: 8 rows x 4 column-pairs, packed f32x2
    u64 acc[8][4];
#pragma unroll
    for (int i = 0; i < 8; i++)
#pragma unroll
        for (int j = 0; j < 4; j++) acc[i][j] = 0ULL;

    for (int k = 0; k < 128; k += 4) {
        float4 a4[8];
#pragma unroll
        for (int i = 0; i < 8; i++)
            a4[i] = *(const float4*)&sA[(r0 + i) * 128 + k];
#pragma unroll
        for (int kk = 0; kk < 4; kk++) {
            float4 b0 = *(const float4*)&sB[(k + kk) * 128 + c0];
            float4 b1 = *(const float4*)&sB[(k + kk) * 128 + c0 + 4];
            u64 bp[4];
            bp[0] = pack2(b0.x, b0.y);
            bp[1] = pack2(b0.z, b0.w);
            bp[2] = pack2(b1.x, b1.y);
            bp[3] = pack2(b1.z, b1.w);
#pragma unroll
            for (int i = 0; i < 8; i++) {
                u64 ad = dup2(((const float*)&a4[i])[kk]);
#pragma unroll
                for (int j = 0; j < 4; j++)
                    acc[i][j] = ffma2(ad, bp[j], acc[i][j]);
            }
        }
    }

    float bv[8];
    if (epi) {
        float4 q0 = ((const float4*)bias)[c0 >> 2];
        float4 q1 = ((const float4*)bias)[(c0 >> 2) + 1];
        bv[0] = q0.x; bv[1] = q0.y; bv[2] = q0.z; bv[3] = q0.w;
        bv[4] = q1.x; bv[5] = q1.y; bv[6] = q1.z; bv[7] = q1.w;
    }
#pragma unroll
    for (int i = 0; i < 8; i++) {
        int gr = row0 + r0 + i;
        if (gr < n) {
            float o[8];
#pragma unroll
            for (int j = 0; j < 4; j++) {
                float2 f = unpack2(acc[i][j]);
                o[2 * j] = f.x;
                o[2 * j + 1] = f.y;
            }
            if (epi) {
#pragma unroll
                for (int j = 0; j < 8; j++) o[j] = fmaxf(o[j] + bv[j], 0.f);
            }
            ((float4*)C)[(size_t)gr * 32 + (c0 >> 2)]     = make_float4(o[0], o[1], o[2], o[3]);
            ((float4*)C)[(size_t)gr * 32 + (c0 >> 2) + 1] = make_float4(o[4], o[5], o[6], o[7]);
        }
    }
}

// ---------------- CSR gather: O[n] = bias + dis[n]^2*T[n] + sum_e w_e*T[src_e] ----------------
// Also accumulates BN stats (sum, sumsq) over h (or relu(h) if relu_first).
__global__ void k_gather(const float* __restrict__ T, const float* __restrict__ bias,
                         float* __restrict__ O, int relu_first) {
    __shared__ float ss[8 * 128];
    __shared__ float sq[8 * 128];
    int t = threadIdx.x;
    int lane = t & 31, wid = t >> 5;
    int gw = blockIdx.x * 8 + wid;
    int tot = gridDim.x * 8;
    float4 b4 = ((const float4*)bias)[lane];
    float lsx = 0, lsy = 0, lsz = 0, lsw = 0;
    float lqx = 0, lqy = 0, lqz = 0, lqw = 0;

    for (int n = gw; n < NN; n += tot) {
        float dn = g_dis[n];
        float sn = dn * dn;
        float4 v = ((const float4*)T)[(size_t)n * 32 + lane];
        float ax = b4.x + sn * v.x;
        float ay = b4.y + sn * v.y;
        float az = b4.z + sn * v.z;
        float aw = b4.w + sn * v.w;
        int s = g_rowptr[n];
        int e = s + g_cnt[n];
        for (int i = s; i < e; i++) {
            int src = __ldg(&g_csrc[i]);
            float w = __ldg(&g_cw[i]);
            float4 u = ((const float4*)T)[(size_t)src * 32 + lane];
            ax += w * u.x; ay += w * u.y; az += w * u.z; aw += w * u.w;
        }
        ((float4*)O)[(size_t)n * 32 + lane] = make_float4(ax, ay, az, aw);
        float rx = ax, ry = ay, rz = az, rw = aw;
        if (relu_first) {
            rx = fmaxf(rx, 0.f); ry = fmaxf(ry, 0.f);
            rz = fmaxf(rz, 0.f); rw = fmaxf(rw, 0.f);
        }
        lsx += rx; lsy += ry; lsz += rz; lsw += rw;
        lqx += rx * rx; lqy += ry * ry; lqz += rz * rz; lqw += rw * rw;
    }
    float* ps = &ss[wid * 128 + lane * 4];
    float* pq = &sq[wid * 128 + lane * 4];
    ps[0] = lsx; ps[1] = lsy; ps[2] = lsz; ps[3] = lsw;
    pq[0] = lqx; pq[1] = lqy; pq[2] = lqz; pq[3] = lqw;
    __syncthreads();
    if (t < 128) {
        float a = 0.f, b = 0.f;
#pragma unroll
        for (int w = 0; w < 8; w++) {
            a += ss[w * 128 + t];
            b += sq[w * 128 + t];
        }
        atomicAdd(&g_stats[t], a);
        atomicAdd(&g_stats[128 + t], b);
    }
}

__global__ void k_zero_stats() {
    if (threadIdx.x < 2 * DD) g_stats[threadIdx.x] = 0.f;
}

// ---------------- output head: sigmoid(h @ w + b) ----------------
__global__ void k_out(const float* __restrict__ H, const float* __restrict__ w,
                      const float* __restrict__ b, float* __restrict__ out) {
    int warp = (blockIdx.x * blockDim.x + threadIdx.x) >> 5;
    int lane = threadIdx.x & 31;
    if (warp >= NN) return;
    float4 h = ((const float4*)H)[(size_t)warp * 32 + lane];
    float4 ww = ((const float4*)w)[lane];
    float s = h.x * ww.x + h.y * ww.y + h.z * ww.z + h.w * ww.w;
#pragma unroll
    for (int o = 16; o; o >>= 1) s += __shfl_down_sync(0xFFFFFFFFu, s, o);
    if (lane == 0) out[warp] = 1.0f / (1.0f + expf(-(s + b[0])));
}

// ---------------- launch ----------------
extern "C" void kernel_launch(void* const* d_in, const int* in_sizes, int n_in,
                              void* d_out, int out_size) {
    const float *x = nullptr, *conv_w = nullptr, *conv_b = nullptr;
    const float *bn_g = nullptr, *bn_b = nullptr, *mlp_w = nullptr, *mlp_b = nullptr;
    const float *out_w = nullptr, *out_b = nullptr;
    const int* ei = nullptr;
    int n256 = 0;
    for (int i = 0; i < n_in; i++) {
        switch (in_sizes[i]) {
            case 6400000: x = (const float*)d_in[i]; break;
            case 1600000: ei = (const int*)d_in[i]; break;
            case 49152:   conv_w = (const float*)d_in[i]; break;
            case 384:     conv_b = (const float*)d_in[i]; break;
            case 32768:   mlp_w = (const float*)d_in[i]; break;
            case 128:     out_w = (const float*)d_in[i]; break;
            case 1:       out_b = (const float*)d_in[i]; break;
            case 256:
                if (n256 == 0) bn_g = (const float*)d_in[i];
                else if (n256 == 1) bn_b = (const float*)d_in[i];
                else mlp_b = (const float*)d_in[i];
                n256++;
                break;
            default: break;
        }
    }

    float *bufA, *bufB, *bufT;
    cudaGetSymbolAddress((void**)&bufA, g_bufA);
    cudaGetSymbolAddress((void**)&bufB, g_bufB);
    cudaGetSymbolAddress((void**)&bufT, g_bufT);

    cudaFuncSetAttribute(k_gemm, cudaFuncAttributeMaxDynamicSharedMemorySize, 131072);

    const int GB = (NN + 127) / 128;  // 391 gemm blocks
    const int NB = (NN + 255) / 256;  // 196
    const int EB = (EE + 255) / 256;  // 3125

    // CSR build (by dst) + degree norm
    k_zero_cnt<<<NB, 256>>>();
    k_hist<<<EB, 256>>>(ei);
    k_deg<<<NB, 256>>>();
    k_scanA<<<SCAN_NT, 128>>>();
    k_scanB<<<1, 512>>>();
    k_scanC<<<SCAN_NT, 128>>>();
    k_fill<<<EB, 256>>>(ei);

    // layer 0: gemm(x) -> gather (+stats0)
    k_zero_stats<<<1, 256>>>();
    k_gemm<<<GB, 256, 131072>>>(x, conv_w, nullptr, bufT, NN, 0, 0, nullptr, nullptr);
    k_gather<<<1184, 256>>>(bufT, conv_b, bufB, 0);

    // layer 1: gemm(relu(bn0(h0))) -> gather (+stats1)
    k_gemm<<<GB, 256, 131072>>>(bufB, conv_w + 1 * 128 * 128, nullptr, bufT, NN, 0, 1, bn_g, bn_b);
    k_zero_stats<<<1, 256>>>();
    k_gather<<<1184, 256>>>(bufT, conv_b + 128, bufB, 0);

    // layer 2: gemm(relu(bn1(h1))) -> gather (+stats over relu(h2))
    k_gemm<<<GB, 256, 131072>>>(bufB, conv_w + 2 * 128 * 128, nullptr, bufT, NN, 0, 1, bn_g + 128, bn_b + 128);
    k_zero_stats<<<1, 256>>>();
    k_gather<<<1184, 256>>>(bufT, conv_b + 256, bufB, 1);

    // mlp1: input = bn1(relu(h2))  (reference quirk), epi = relu(.+b)
    k_gemm<<<GB, 256, 131072>>>(bufB, mlp_w, mlp_b, bufA, NN, 1, 2, bn_g + 128, bn_b + 128);
    // mlp2
    k_gemm<<<GB, 256, 131072>>>(bufA, mlp_w + 128 * 128, mlp_b + 128, bufB, NN, 1, 0, nullptr, nullptr);

    k_out<<<(NN * 32 + 255) / 256, 256>>>(bufB, out_w, out_b, (float*)d_out);
}

// round 6
// speedup vs baseline: 2.1742x; 1.3464x over previous
#include <cuda_runtime.h>
#include <cuda_bf16.h>
#include <math.h>

#define NN 50000
#define EE 800000
#define DD 128
#define BN_EPS 1e-5f
#define SCAN_CHUNK 128
#define SCAN_NT ((NN + SCAN_CHUNK - 1) / SCAN_CHUNK)   // 391

typedef unsigned long long u64;
typedef unsigned int u32;
typedef unsigned short u16;

// ---------------- scratch (no allocs allowed) ----------------
__device__ float g_bufA[NN * DD];
__device__ float g_bufB[NN * DD];
__device__ float g_bufT[NN * DD];
__device__ float g_dis[NN];
__device__ float g_stats[2 * DD];
__device__ int   g_cnt[NN];
__device__ int   g_rowptr[NN];
__device__ int   g_cursor[NN];
__device__ int   g_csrc[EE];
__device__ float g_cw[EE];
__device__ int   g_tsum[512];
// W transposed to [fout][k], bf16 hi/lo, 5 matrices
__device__ u16 g_whi[5 * 16384];
__device__ u16 g_wlo[5 * 16384];

// ---------------- mma helpers ----------------
__device__ __forceinline__ u32 su32(const void* p) {
    return (u32)__cvta_generic_to_shared(p);
}
__device__ __forceinline__ void ldsm_x4(u32& r0, u32& r1, u32& r2, u32& r3, u32 addr) {
    asm volatile("ldmatrix.sync.aligned.m8n8.x4.shared.b16 {%0,%1,%2,%3}, [%4];"
                 : "=r"(r0), "=r"(r1), "=r"(r2), "=r"(r3) : "r"(addr));
}
__device__ __forceinline__ void ldsm_x2(u32& r0, u32& r1, u32 addr) {
    asm volatile("ldmatrix.sync.aligned.m8n8.x2.shared.b16 {%0,%1}, [%2];"
                 : "=r"(r0), "=r"(r1) : "r"(addr));
}
__device__ __forceinline__ void mma16816(float* c, const u32* a, const u32* b) {
    asm volatile(
        "mma.sync.aligned.m16n8k16.row.col.f32.bf16.bf16.f32 "
        "{%0,%1,%2,%3}, {%4,%5,%6,%7}, {%8,%9}, {%0,%1,%2,%3};"
        : "+f"(c[0]), "+f"(c[1]), "+f"(c[2]), "+f"(c[3])
        : "r"(a[0]), "r"(a[1]), "r"(a[2]), "r"(a[3]), "r"(b[0]), "r"(b[1]));
}

// ---------------- weight prep: transpose + bf16 split ----------------
__global__ void k_prep_w(const float* __restrict__ conv_w, const float* __restrict__ mlp_w) {
    int idx = blockIdx.x * blockDim.x + threadIdx.x;
    if (idx >= 5 * 16384) return;
    int w = idx >> 14;
    int r = idx & 16383;
    int fout = r >> 7;
    int k = r & 127;
    float v = (w < 3) ? conv_w[w * 16384 + k * 128 + fout]
                      : mlp_w[(w - 3) * 16384 + k * 128 + fout];
    __nv_bfloat16 hi = __float2bfloat16_rn(v);
    __nv_bfloat16 lo = __float2bfloat16_rn(v - __bfloat162float(hi));
    g_whi[w * 16384 + fout * 128 + k] = __bfloat16_as_ushort(hi);
    g_wlo[w * 16384 + fout * 128 + k] = __bfloat16_as_ushort(lo);
}

// ---------------- CSR build ----------------
__global__ void k_zero_cnt() {
    int i = blockIdx.x * blockDim.x + threadIdx.x;
    if (i < NN) g_cnt[i] = 0;
}
__global__ void k_hist(const int* __restrict__ ei) {
    int e = blockIdx.x * blockDim.x + threadIdx.x;
    if (e < EE) atomicAdd(&g_cnt[ei[EE + e]], 1);
}
__global__ void k_deg() {
    int i = blockIdx.x * blockDim.x + threadIdx.x;
    if (i < NN) g_dis[i] = rsqrtf((float)g_cnt[i] + 1.0f);  // +1 self-loop
}
__global__ void k_scanA() {
    __shared__ int sh[4];
    int t = threadIdx.x;
    int i = blockIdx.x * 128 + t;
    int v = (i < NN) ? g_cnt[i] : 0;
#pragma unroll
    for (int o = 16; o; o >>= 1) v += __shfl_down_sync(0xFFFFFFFFu, v, o);
    if ((t & 31) == 0) sh[t >> 5] = v;
    __syncthreads();
    if (t == 0) g_tsum[blockIdx.x] = sh[0] + sh[1] + sh[2] + sh[3];
}
__global__ void k_scanB() {
    __shared__ int s[512];
    int t = threadIdx.x;
    int v = (t < SCAN_NT) ? g_tsum[t] : 0;
    s[t] = v;
    __syncthreads();
    for (int o = 1; o < 512; o <<= 1) {
        int x = (t >= o) ? s[t - o] : 0;
        __syncthreads();
        s[t] += x;
        __syncthreads();
    }
    if (t < SCAN_NT) g_tsum[t] = s[t] - v;
}
__global__ void k_scanC() {
    __shared__ int sh[128];
    int t = threadIdx.x;
    int i = blockIdx.x * 128 + t;
    int v = (i < NN) ? g_cnt[i] : 0;
    sh[t] = v;
    __syncthreads();
    for (int o = 1; o < 128; o <<= 1) {
        int x = (t >= o) ? sh[t - o] : 0;
        __syncthreads();
        sh[t] += x;
        __syncthreads();
    }
    if (i < NN) {
        int ex = sh[t] - v + g_tsum[blockIdx.x];
        g_rowptr[i] = ex;
        g_cursor[i] = ex;
    }
}
__global__ void k_fill(const int* __restrict__ ei) {
    int e = blockIdx.x * blockDim.x + threadIdx.x;
    if (e >= EE) return;
    int src = ei[e];
    int dst = ei[EE + e];
    int pos = atomicAdd(&g_cursor[dst], 1);
    g_csrc[pos] = src;
    g_cw[pos] = g_dis[src] * g_dis[dst];
}

// ---------------- tensor-core GEMM via mma.sync (bf16 3-split) ----------------
// C[node,fout] = f(X)[node,:] @ W.  A = X tile (row-major), B = Wt [fout][k].
// tmode: 0 identity, 1 relu(bn(v)), 2 bn(relu(v));  epi: 1 = relu(.+bias)
// smem layout (bytes): sWh:0, sWl:34816, sAh:69632, sAl:104448  (each 128x136 bf16)
#define PADK 136
#define IMG (128 * PADK * 2)
extern __shared__ char s_dyn[];
__global__ void __launch_bounds__(256, 1)
k_gemm_mma(const float* __restrict__ X, const u16* __restrict__ Wh,
           const u16* __restrict__ Wl, const float* __restrict__ bias,
           float* __restrict__ C, int n, int epi, int tmode,
           const float* __restrict__ gamma, const float* __restrict__ beta) {
    __shared__ float s_scale[128], s_shift[128];
    char* sm = s_dyn;
    int t = threadIdx.x;
    int lane = t & 31, wid = t >> 5;
    int row0 = blockIdx.x * 128;

    if (tmode && t < 128) {
        float inv = 1.0f / (float)NN;
        float mean = g_stats[t] * inv;
        float var = g_stats[128 + t] * inv - mean * mean;
        float rs = rsqrtf(var + BN_EPS);
        float sc = rs * gamma[t];
        s_scale[t] = sc;
        s_shift[t] = beta[t] - mean * sc;
    }
    __syncthreads();

    // copy W images into padded smem (8 bf16 = 1 float4 per chunk; 2048 chunks each)
#pragma unroll
    for (int i = 0; i < 8; i++) {
        int idx = i * 256 + t;
        int row = idx >> 4, c8 = idx & 15;
        int off = row * PADK * 2 + c8 * 16;
        *(float4*)(sm + off) = ((const float4*)Wh)[idx];
        *(float4*)(sm + IMG + off) = ((const float4*)Wl)[idx];
    }

    // load + transform + split X tile into sAh/sAl
#pragma unroll
    for (int i = 0; i < 16; i++) {
        int idx = i * 256 + t;  // float4 index in [0,4096)
        int row = idx >> 5;
        int c4 = idx & 31;
        int gr = row0 + row;
        float4 v = (gr < n) ? ((const float4*)X)[(size_t)gr * 32 + c4]
                            : make_float4(0.f, 0.f, 0.f, 0.f);
        float vv[4] = {v.x, v.y, v.z, v.w};
        if (tmode) {
            int c0 = c4 * 4;
#pragma unroll
            for (int j = 0; j < 4; j++) {
                float xv = vv[j];
                if (tmode == 2) xv = fmaxf(xv, 0.f);
                float y = xv * s_scale[c0 + j] + s_shift[c0 + j];
                if (tmode == 1) y = fmaxf(y, 0.f);
                vv[j] = y;
            }
        }
        u32 hw[2], lw[2];
#pragma unroll
        for (int j = 0; j < 2; j++) {
            __nv_bfloat16 h0 = __float2bfloat16_rn(vv[2 * j]);
            __nv_bfloat16 h1 = __float2bfloat16_rn(vv[2 * j + 1]);
            __nv_bfloat16 l0 = __float2bfloat16_rn(vv[2 * j] - __bfloat162float(h0));
            __nv_bfloat16 l1 = __float2bfloat16_rn(vv[2 * j + 1] - __bfloat162float(h1));
            hw[j] = ((u32)__bfloat16_as_ushort(h1) << 16) | __bfloat16_as_ushort(h0);
            lw[j] = ((u32)__bfloat16_as_ushort(l1) << 16) | __bfloat16_as_ushort(l0);
        }
        int off = row * PADK * 2 + c4 * 8;  // bytes
        *(u32*)(sm + 2 * IMG + off) = hw[0];
        *(u32*)(sm + 2 * IMG + off + 4) = hw[1];
        *(u32*)(sm + 3 * IMG + off) = lw[0];
        *(u32*)(sm + 3 * IMG + off + 4) = lw[1];
    }
    __syncthreads();

    int mw = wid >> 2, nw = wid & 3;  // 2 x 4 warp grid
    float acc[4][4][4];
#pragma unroll
    for (int mt = 0; mt < 4; mt++)
#pragma unroll
        for (int nt = 0; nt < 4; nt++)
#pragma unroll
            for (int j = 0; j < 4; j++) acc[mt][nt][j] = 0.f;

    u32 sW_base[3], sA_base[3];
    sW_base[0] = su32(sm);             sA_base[0] = su32(sm + 2 * IMG);  // hi*hi
    sW_base[1] = su32(sm + IMG);       sA_base[1] = su32(sm + 2 * IMG);  // hi*Wlo
    sW_base[2] = su32(sm);             sA_base[2] = su32(sm + 3 * IMG);  // lo*Whi

    int a_row = mw * 64 + (lane & 15);
    int a_coff = (lane >> 4) * 8;
    int b_row = nw * 32 + (lane & 7);
    int b_coff = ((lane >> 3) & 1) * 8;

#pragma unroll
    for (int p = 0; p < 3; p++) {
        u32 aB = sA_base[p], wB = sW_base[p];
#pragma unroll
        for (int ks = 0; ks < 8; ks++) {
            int kc = ks * 16;
            u32 a[4][4], b[4][2];
#pragma unroll
            for (int mt = 0; mt < 4; mt++)
                ldsm_x4(a[mt][0], a[mt][1], a[mt][2], a[mt][3],
                        aB + (u32)(((a_row + mt * 16) * PADK + kc + a_coff) * 2));
#pragma unroll
            for (int nt = 0; nt < 4; nt++)
                ldsm_x2(b[nt][0], b[nt][1],
                        wB + (u32)(((b_row + nt * 8) * PADK + kc + b_coff) * 2));
#pragma unroll
            for (int mt = 0; mt < 4; mt++)
#pragma unroll
                for (int nt = 0; nt < 4; nt++)
                    mma16816(acc[mt][nt], a[mt], b[nt]);
        }
    }

    // epilogue: c0,c1 -> row g, cols q*2..+1 ; c2,c3 -> row g+8
    int g = lane >> 2, q = lane & 3;
#pragma unroll
    for (int mt = 0; mt < 4; mt++) {
        int r0g = row0 + mw * 64 + mt * 16 + g;
#pragma unroll
        for (int nt = 0; nt < 4; nt++) {
            int col = nw * 32 + nt * 8 + q * 2;
            float v0 = acc[mt][nt][0], v1 = acc[mt][nt][1];
            float v2 = acc[mt][nt][2], v3 = acc[mt][nt][3];
            if (epi) {
                float2 bb = *(const float2*)&bias[col];
                v0 = fmaxf(v0 + bb.x, 0.f); v1 = fmaxf(v1 + bb.y, 0.f);
                v2 = fmaxf(v2 + bb.x, 0.f); v3 = fmaxf(v3 + bb.y, 0.f);
            }
            if (r0g < n)     *(float2*)&C[(size_t)r0g * 128 + col] = make_float2(v0, v1);
            if (r0g + 8 < n) *(float2*)&C[(size_t)(r0g + 8) * 128 + col] = make_float2(v2, v3);
        }
    }
}

// ---------------- CSR gather + fused BN stats ----------------
__global__ void k_gather(const float* __restrict__ T, const float* __restrict__ bias,
                         float* __restrict__ O, int relu_first) {
    __shared__ float ss[8 * 128];
    __shared__ float sq[8 * 128];
    int t = threadIdx.x;
    int lane = t & 31, wid = t >> 5;
    int gw = blockIdx.x * 8 + wid;
    int tot = gridDim.x * 8;
    float4 b4 = ((const float4*)bias)[lane];
    float lsx = 0, lsy = 0, lsz = 0, lsw = 0;
    float lqx = 0, lqy = 0, lqz = 0, lqw = 0;

    for (int n = gw; n < NN; n += tot) {
        float dn = g_dis[n];
        float sn = dn * dn;
        float4 v = ((const float4*)T)[(size_t)n * 32 + lane];
        float ax = b4.x + sn * v.x;
        float ay = b4.y + sn * v.y;
        float az = b4.z + sn * v.z;
        float aw = b4.w + sn * v.w;
        int s = g_rowptr[n];
        int e = s + g_cnt[n];
        for (int i = s; i < e; i++) {
            int src = __ldg(&g_csrc[i]);
            float w = __ldg(&g_cw[i]);
            float4 u = ((const float4*)T)[(size_t)src * 32 + lane];
            ax += w * u.x; ay += w * u.y; az += w * u.z; aw += w * u.w;
        }
        ((float4*)O)[(size_t)n * 32 + lane] = make_float4(ax, ay, az, aw);
        float rx = ax, ry = ay, rz = az, rw = aw;
        if (relu_first) {
            rx = fmaxf(rx, 0.f); ry = fmaxf(ry, 0.f);
            rz = fmaxf(rz, 0.f); rw = fmaxf(rw, 0.f);
        }
        lsx += rx; lsy += ry; lsz += rz; lsw += rw;
        lqx += rx * rx; lqy += ry * ry; lqz += rz * rz; lqw += rw * rw;
    }
    float* ps = &ss[wid * 128 + lane * 4];
    float* pq = &sq[wid * 128 + lane * 4];
    ps[0] = lsx; ps[1] = lsy; ps[2] = lsz; ps[3] = lsw;
    pq[0] = lqx; pq[1] = lqy; pq[2] = lqz; pq[3] = lqw;
    __syncthreads();
    if (t < 128) {
        float a = 0.f, b = 0.f;
#pragma unroll
        for (int w = 0; w < 8; w++) {
            a += ss[w * 128 + t];
            b += sq[w * 128 + t];
        }
        atomicAdd(&g_stats[t], a);
        atomicAdd(&g_stats[128 + t], b);
    }
}

__global__ void k_zero_stats() {
    if (threadIdx.x < 2 * DD) g_stats[threadIdx.x] = 0.f;
}

// ---------------- output head: sigmoid(h @ w + b) ----------------
__global__ void k_out(const float* __restrict__ H, const float* __restrict__ w,
                      const float* __restrict__ b, float* __restrict__ out) {
    int warp = (blockIdx.x * blockDim.x + threadIdx.x) >> 5;
    int lane = threadIdx.x & 31;
    if (warp >= NN) return;
    float4 h = ((const float4*)H)[(size_t)warp * 32 + lane];
    float4 ww = ((const float4*)w)[lane];
    float s = h.x * ww.x + h.y * ww.y + h.z * ww.z + h.w * ww.w;
#pragma unroll
    for (int o = 16; o; o >>= 1) s += __shfl_down_sync(0xFFFFFFFFu, s, o);
    if (lane == 0) out[warp] = 1.0f / (1.0f + expf(-(s + b[0])));
}

// ---------------- launch ----------------
extern "C" void kernel_launch(void* const* d_in, const int* in_sizes, int n_in,
                              void* d_out, int out_size) {
    const float *x = nullptr, *conv_w = nullptr, *conv_b = nullptr;
    const float *bn_g = nullptr, *bn_b = nullptr, *mlp_w = nullptr, *mlp_b = nullptr;
    const float *out_w = nullptr, *out_b = nullptr;
    const int* ei = nullptr;
    int n256 = 0;
    for (int i = 0; i < n_in; i++) {
        switch (in_sizes[i]) {
            case 6400000: x = (const float*)d_in[i]; break;
            case 1600000: ei = (const int*)d_in[i]; break;
            case 49152:   conv_w = (const float*)d_in[i]; break;
            case 384:     conv_b = (const float*)d_in[i]; break;
            case 32768:   mlp_w = (const float*)d_in[i]; break;
            case 128:     out_w = (const float*)d_in[i]; break;
            case 1:       out_b = (const float*)d_in[i]; break;
            case 256:
                if (n256 == 0) bn_g = (const float*)d_in[i];
                else if (n256 == 1) bn_b = (const float*)d_in[i];
                else mlp_b = (const float*)d_in[i];
                n256++;
                break;
            default: break;
        }
    }

    float *bufA, *bufB, *bufT;
    u16 *whi, *wlo;
    cudaGetSymbolAddress((void**)&bufA, g_bufA);
    cudaGetSymbolAddress((void**)&bufB, g_bufB);
    cudaGetSymbolAddress((void**)&bufT, g_bufT);
    cudaGetSymbolAddress((void**)&whi, g_whi);
    cudaGetSymbolAddress((void**)&wlo, g_wlo);

    const int SMEM = 4 * IMG;  // 139264
    cudaFuncSetAttribute(k_gemm_mma, cudaFuncAttributeMaxDynamicSharedMemorySize, SMEM);

    const int GB = (NN + 127) / 128;  // 391 tiles
    const int NB = (NN + 255) / 256;
    const int EB = (EE + 255) / 256;

    // weight prep + CSR build
    k_prep_w<<<(5 * 16384 + 255) / 256, 256>>>(conv_w, mlp_w);
    k_zero_cnt<<<NB, 256>>>();
    k_hist<<<EB, 256>>>(ei);
    k_deg<<<NB, 256>>>();
    k_scanA<<<SCAN_NT, 128>>>();
    k_scanB<<<1, 512>>>();
    k_scanC<<<SCAN_NT, 128>>>();
    k_fill<<<EB, 256>>>(ei);

    // layer 0
    k_zero_stats<<<1, 256>>>();
    k_gemm_mma<<<GB, 256, SMEM>>>(x, whi, wlo, nullptr, bufT, NN, 0, 0, nullptr, nullptr);
    k_gather<<<1184, 256>>>(bufT, conv_b, bufB, 0);

    // layer 1
    k_gemm_mma<<<GB, 256, SMEM>>>(bufB, whi + 16384, wlo + 16384, nullptr, bufT, NN, 0, 1, bn_g, bn_b);
    k_zero_stats<<<1, 256>>>();
    k_gather<<<1184, 256>>>(bufT, conv_b + 128, bufB, 0);

    // layer 2
    k_gemm_mma<<<GB, 256, SMEM>>>(bufB, whi + 32768, wlo + 32768, nullptr, bufT, NN, 0, 1, bn_g + 128, bn_b + 128);
    k_zero_stats<<<1, 256>>>();
    k_gather<<<1184, 256>>>(bufT, conv_b + 256, bufB, 1);

    // mlp1 (tmode 2: bn1(relu(h2)) — reference quirk), epi relu(+bias)
    k_gemm_mma<<<GB, 256, SMEM>>>(bufB, whi + 49152, wlo + 49152, mlp_b, bufA, NN, 1, 2, bn_g + 128, bn_b + 128);
    // mlp2
    k_gemm_mma<<<GB, 256, SMEM>>>(bufA, whi + 65536, wlo + 65536, mlp_b + 128, bufB, NN, 1, 0, nullptr, nullptr);

    k_out<<<(NN * 32 + 255) / 256, 256>>>(bufB, out_w, out_b, (float*)d_out);
}

// round 7
// speedup vs baseline: 2.2633x; 1.0410x over previous
#include <cuda_runtime.h>
#include <cuda_bf16.h>
#include <cuda_fp16.h>
#include <math.h>

#define NN 50000
#define EE 800000
#define DD 128
#define BN_EPS 1e-5f
#define SCAN_NT ((NN + 127) / 128)   // 391

typedef unsigned long long u64;
typedef unsigned int u32;
typedef unsigned short u16;

// ---------------- scratch (no allocs allowed) ----------------
__device__ float  g_bufA[NN * DD];
__device__ float  g_bufB[NN * DD];
__device__ __half g_bufTh[NN * DD];
__device__ float  g_dis[NN];
__device__ float  g_stats3[3 * 256];
__device__ int    g_cnt[NN];
__device__ int    g_rowptr[NN];
__device__ int    g_cursor[NN];
__device__ int    g_csrc[EE];
__device__ float  g_cw[EE];
__device__ int    g_tsum[512];
__device__ u16    g_whi[5 * 16384];
__device__ u16    g_wlo[5 * 16384];

// ---------------- mma helpers ----------------
__device__ __forceinline__ u32 su32(const void* p) {
    return (u32)__cvta_generic_to_shared(p);
}
__device__ __forceinline__ void ldsm_x4(u32& r0, u32& r1, u32& r2, u32& r3, u32 addr) {
    asm volatile("ldmatrix.sync.aligned.m8n8.x4.shared.b16 {%0,%1,%2,%3}, [%4];"
                 : "=r"(r0), "=r"(r1), "=r"(r2), "=r"(r3) : "r"(addr));
}
__device__ __forceinline__ void ldsm_x2(u32& r0, u32& r1, u32 addr) {
    asm volatile("ldmatrix.sync.aligned.m8n8.x2.shared.b16 {%0,%1}, [%2];"
                 : "=r"(r0), "=r"(r1) : "r"(addr));
}
__device__ __forceinline__ void mma16816(float* c, const u32* a, const u32* b) {
    asm volatile(
        "mma.sync.aligned.m16n8k16.row.col.f32.bf16.bf16.f32 "
        "{%0,%1,%2,%3}, {%4,%5,%6,%7}, {%8,%9}, {%0,%1,%2,%3};"
        : "+f"(c[0]), "+f"(c[1]), "+f"(c[2]), "+f"(c[3])
        : "r"(a[0]), "r"(a[1]), "r"(a[2]), "r"(a[3]), "r"(b[0]), "r"(b[1]));
}

// ---------------- weight prep + zero cnt/stats ----------------
__global__ void k_prep_w(const float* __restrict__ conv_w, const float* __restrict__ mlp_w) {
    int idx = blockIdx.x * blockDim.x + threadIdx.x;
    if (idx < NN) g_cnt[idx] = 0;
    if (idx < 3 * 256) g_stats3[idx] = 0.f;
    if (idx >= 5 * 16384) return;
    int w = idx >> 14;
    int r = idx & 16383;
    int fout = r >> 7;
    int k = r & 127;
    float v = (w < 3) ? conv_w[w * 16384 + k * 128 + fout]
                      : mlp_w[(w - 3) * 16384 + k * 128 + fout];
    __nv_bfloat16 hi = __float2bfloat16_rn(v);
    __nv_bfloat16 lo = __float2bfloat16_rn(v - __bfloat162float(hi));
    g_whi[idx] = __bfloat16_as_ushort(hi);   // layout [w][fout][k]
    g_wlo[idx] = __bfloat16_as_ushort(lo);
}

// ---------------- CSR build ----------------
__global__ void k_hist(const int* __restrict__ ei) {
    int e = blockIdx.x * blockDim.x + threadIdx.x;
    if (e < EE) atomicAdd(&g_cnt[ei[EE + e]], 1);
}
// tile sums + deg norm
__global__ void k_scanA() {
    __shared__ int sh[4];
    int t = threadIdx.x;
    int i = blockIdx.x * 128 + t;
    int c = (i < NN) ? g_cnt[i] : 0;
    if (i < NN) g_dis[i] = rsqrtf((float)c + 1.0f);  // +1 self-loop
    int v = c;
#pragma unroll
    for (int o = 16; o; o >>= 1) v += __shfl_down_sync(0xFFFFFFFFu, v, o);
    if ((t & 31) == 0) sh[t >> 5] = v;
    __syncthreads();
    if (t == 0) g_tsum[blockIdx.x] = sh[0] + sh[1] + sh[2] + sh[3];
}
__global__ void k_scanB() {
    __shared__ int s[512];
    int t = threadIdx.x;
    int v = (t < SCAN_NT) ? g_tsum[t] : 0;
    s[t] = v;
    __syncthreads();
    for (int o = 1; o < 512; o <<= 1) {
        int x = (t >= o) ? s[t - o] : 0;
        __syncthreads();
        s[t] += x;
        __syncthreads();
    }
    if (t < SCAN_NT) g_tsum[t] = s[t] - v;
}
__global__ void k_scanC() {
    __shared__ int sh[128];
    int t = threadIdx.x;
    int i = blockIdx.x * 128 + t;
    int v = (i < NN) ? g_cnt[i] : 0;
    sh[t] = v;
    __syncthreads();
    for (int o = 1; o < 128; o <<= 1) {
        int x = (t >= o) ? sh[t - o] : 0;
        __syncthreads();
        sh[t] += x;
        __syncthreads();
    }
    if (i < NN) {
        int ex = sh[t] - v + g_tsum[blockIdx.x];
        g_rowptr[i] = ex;
        g_cursor[i] = ex;
    }
}
__global__ void k_fill(const int* __restrict__ ei) {
    int e = blockIdx.x * blockDim.x + threadIdx.x;
    if (e >= EE) return;
    int src = ei[e];
    int dst = ei[EE + e];
    int pos = atomicAdd(&g_cursor[dst], 1);
    g_csrc[pos] = src;
    g_cw[pos] = g_dis[src] * g_dis[dst];
}

// ---------------- tensor-core GEMM (bf16 3-split) ----------------
// omode: 0 = store fp16 to Th; 1 = relu(.+bias) fp32 to Cf; 2 = fused sigmoid head -> dout
// tmode: 0 identity, 1 relu(bn(v)), 2 bn(relu(v))   (bn from stats[])
#define PADK 136
#define IMG (128 * PADK * 2)
extern __shared__ char s_dyn[];
__global__ void __launch_bounds__(256, 1)
k_gemm_mma(const float* __restrict__ X, const u16* __restrict__ Wh,
           const u16* __restrict__ Wl, const float* __restrict__ bias,
           float* __restrict__ Cf, __half* __restrict__ Th,
           int n, int omode, int tmode,
           const float* __restrict__ gamma, const float* __restrict__ beta,
           const float* __restrict__ stats,
           const float* __restrict__ ow, const float* __restrict__ ob,
           float* __restrict__ dout) {
    __shared__ float s_scale[128], s_shift[128];
    __shared__ float s_part[128][4];
    char* sm = s_dyn;
    int t = threadIdx.x;
    int lane = t & 31, wid = t >> 5;
    int row0 = blockIdx.x * 128;

    if (tmode && t < 128) {
        float inv = 1.0f / (float)NN;
        float mean = stats[t] * inv;
        float var = stats[128 + t] * inv - mean * mean;
        float rs = rsqrtf(var + BN_EPS);
        float sc = rs * gamma[t];
        s_scale[t] = sc;
        s_shift[t] = beta[t] - mean * sc;
    }
    __syncthreads();

    // W images into padded smem
#pragma unroll
    for (int i = 0; i < 8; i++) {
        int idx = i * 256 + t;
        int row = idx >> 4, c8 = idx & 15;
        int off = row * PADK * 2 + c8 * 16;
        *(float4*)(sm + off) = ((const float4*)Wh)[idx];
        *(float4*)(sm + IMG + off) = ((const float4*)Wl)[idx];
    }

    // X tile: load fp32, transform, split to bf16 hi/lo
#pragma unroll
    for (int i = 0; i < 16; i++) {
        int idx = i * 256 + t;
        int row = idx >> 5;
        int c4 = idx & 31;
        int gr = row0 + row;
        float4 v = (gr < n) ? ((const float4*)X)[(size_t)gr * 32 + c4]
                            : make_float4(0.f, 0.f, 0.f, 0.f);
        float vv[4] = {v.x, v.y, v.z, v.w};
        if (tmode) {
            int c0 = c4 * 4;
#pragma unroll
            for (int j = 0; j < 4; j++) {
                float xv = vv[j];
                if (tmode == 2) xv = fmaxf(xv, 0.f);
                float y = xv * s_scale[c0 + j] + s_shift[c0 + j];
                if (tmode == 1) y = fmaxf(y, 0.f);
                vv[j] = y;
            }
        }
        u32 hw[2], lw[2];
#pragma unroll
        for (int j = 0; j < 2; j++) {
            __nv_bfloat16 h0 = __float2bfloat16_rn(vv[2 * j]);
            __nv_bfloat16 h1 = __float2bfloat16_rn(vv[2 * j + 1]);
            __nv_bfloat16 l0 = __float2bfloat16_rn(vv[2 * j] - __bfloat162float(h0));
            __nv_bfloat16 l1 = __float2bfloat16_rn(vv[2 * j + 1] - __bfloat162float(h1));
            hw[j] = ((u32)__bfloat16_as_ushort(h1) << 16) | __bfloat16_as_ushort(h0);
            lw[j] = ((u32)__bfloat16_as_ushort(l1) << 16) | __bfloat16_as_ushort(l0);
        }
        int off = row * PADK * 2 + c4 * 8;
        *(u32*)(sm + 2 * IMG + off) = hw[0];
        *(u32*)(sm + 2 * IMG + off + 4) = hw[1];
        *(u32*)(sm + 3 * IMG + off) = lw[0];
        *(u32*)(sm + 3 * IMG + off + 4) = lw[1];
    }
    __syncthreads();

    int mw = wid >> 2, nw = wid & 3;
    float acc[4][4][4];
#pragma unroll
    for (int mt = 0; mt < 4; mt++)
#pragma unroll
        for (int nt = 0; nt < 4; nt++)
#pragma unroll
            for (int j = 0; j < 4; j++) acc[mt][nt][j] = 0.f;

    u32 sW_base[3], sA_base[3];
    sW_base[0] = su32(sm);       sA_base[0] = su32(sm + 2 * IMG);
    sW_base[1] = su32(sm + IMG); sA_base[1] = su32(sm + 2 * IMG);
    sW_base[2] = su32(sm);       sA_base[2] = su32(sm + 3 * IMG);

    int a_row = mw * 64 + (lane & 15);
    int a_coff = (lane >> 4) * 8;
    int b_row = nw * 32 + (lane & 7);
    int b_coff = ((lane >> 3) & 1) * 8;

#pragma unroll
    for (int p = 0; p < 3; p++) {
        u32 aB = sA_base[p], wB = sW_base[p];
#pragma unroll
        for (int ks = 0; ks < 8; ks++) {
            int kc = ks * 16;
            u32 a[4][4], b[4][2];
#pragma unroll
            for (int mt = 0; mt < 4; mt++)
                ldsm_x4(a[mt][0], a[mt][1], a[mt][2], a[mt][3],
                        aB + (u32)(((a_row + mt * 16) * PADK + kc + a_coff) * 2));
#pragma unroll
            for (int nt = 0; nt < 4; nt++)
                ldsm_x2(b[nt][0], b[nt][1],
                        wB + (u32)(((b_row + nt * 8) * PADK + kc + b_coff) * 2));
#pragma unroll
            for (int mt = 0; mt < 4; mt++)
#pragma unroll
                for (int nt = 0; nt < 4; nt++)
                    mma16816(acc[mt][nt], a[mt], b[nt]);
        }
    }

    // epilogue
    int g = lane >> 2, q = lane & 3;
#pragma unroll
    for (int mt = 0; mt < 4; mt++) {
        int rl1 = mw * 64 + mt * 16 + g;
        int r1 = row0 + rl1, r2 = r1 + 8;
        float p1 = 0.f, p2 = 0.f;
#pragma unroll
        for (int nt = 0; nt < 4; nt++) {
            int col = nw * 32 + nt * 8 + q * 2;
            float v0 = acc[mt][nt][0], v1 = acc[mt][nt][1];
            float v2 = acc[mt][nt][2], v3 = acc[mt][nt][3];
            if (omode >= 1) {
                float2 bb = *(const float2*)&bias[col];
                v0 = fmaxf(v0 + bb.x, 0.f); v1 = fmaxf(v1 + bb.y, 0.f);
                v2 = fmaxf(v2 + bb.x, 0.f); v3 = fmaxf(v3 + bb.y, 0.f);
            }
            if (omode == 0) {
                if (r1 < n) *(half2*)&Th[(size_t)r1 * 128 + col] = __floats2half2_rn(v0, v1);
                if (r2 < n) *(half2*)&Th[(size_t)r2 * 128 + col] = __floats2half2_rn(v2, v3);
            } else if (omode == 1) {
                if (r1 < n) *(float2*)&Cf[(size_t)r1 * 128 + col] = make_float2(v0, v1);
                if (r2 < n) *(float2*)&Cf[(size_t)r2 * 128 + col] = make_float2(v2, v3);
            } else {
                float w0 = __ldg(&ow[col]), w1 = __ldg(&ow[col + 1]);
                p1 += v0 * w0 + v1 * w1;
                p2 += v2 * w0 + v3 * w1;
            }
        }
        if (omode == 2) {
            p1 += __shfl_down_sync(0xFFFFFFFFu, p1, 1, 4);
            p1 += __shfl_down_sync(0xFFFFFFFFu, p1, 2, 4);
            p2 += __shfl_down_sync(0xFFFFFFFFu, p2, 1, 4);
            p2 += __shfl_down_sync(0xFFFFFFFFu, p2, 2, 4);
            if (q == 0) {
                s_part[rl1][nw] = p1;
                s_part[rl1 + 8][nw] = p2;
            }
        }
    }
    if (omode == 2) {
        __syncthreads();
        if (t < 128) {
            int gr = row0 + t;
            if (gr < n) {
                float s = s_part[t][0] + s_part[t][1] + s_part[t][2] + s_part[t][3] + ob[0];
                dout[gr] = 1.0f / (1.0f + expf(-s));
            }
        }
    }
}

// ---------------- CSR gather (fp16 messages) + fused BN stats ----------------
__global__ void k_gather(const __half* __restrict__ Th, const float* __restrict__ bias,
                         float* __restrict__ O, float* __restrict__ stats, int relu_first) {
    __shared__ float ss[8 * 128];
    __shared__ float sq[8 * 128];
    int t = threadIdx.x;
    int lane = t & 31, wid = t >> 5;
    int gw = blockIdx.x * 8 + wid;
    int tot = gridDim.x * 8;
    float4 b4 = ((const float4*)bias)[lane];
    float lsx = 0, lsy = 0, lsz = 0, lsw = 0;
    float lqx = 0, lqy = 0, lqz = 0, lqw = 0;

    for (int n = gw; n < NN; n += tot) {
        float dn = g_dis[n];
        float sn = dn * dn;
        uint2 tv = *(const uint2*)&Th[(size_t)n * 128 + lane * 4];
        float2 f0 = __half22float2(*(half2*)&tv.x);
        float2 f1 = __half22float2(*(half2*)&tv.y);
        float ax = b4.x + sn * f0.x;
        float ay = b4.y + sn * f0.y;
        float az = b4.z + sn * f1.x;
        float aw = b4.w + sn * f1.y;
        int s = g_rowptr[n];
        int e = s + g_cnt[n];
        int i = s;
        for (; i + 1 < e; i += 2) {
            int s0 = __ldg(&g_csrc[i]);
            int s1 = __ldg(&g_csrc[i + 1]);
            float w0 = __ldg(&g_cw[i]);
            float w1 = __ldg(&g_cw[i + 1]);
            uint2 u0 = *(const uint2*)&Th[(size_t)s0 * 128 + lane * 4];
            uint2 u1 = *(const uint2*)&Th[(size_t)s1 * 128 + lane * 4];
            float2 a0 = __half22float2(*(half2*)&u0.x);
            float2 a1 = __half22float2(*(half2*)&u0.y);
            float2 c0 = __half22float2(*(half2*)&u1.x);
            float2 c1 = __half22float2(*(half2*)&u1.y);
            ax += w0 * a0.x + w1 * c0.x;
            ay += w0 * a0.y + w1 * c0.y;
            az += w0 * a1.x + w1 * c1.x;
            aw += w0 * a1.y + w1 * c1.y;
        }
        if (i < e) {
            int s0 = __ldg(&g_csrc[i]);
            float w0 = __ldg(&g_cw[i]);
            uint2 u0 = *(const uint2*)&Th[(size_t)s0 * 128 + lane * 4];
            float2 a0 = __half22float2(*(half2*)&u0.x);
            float2 a1 = __half22float2(*(half2*)&u0.y);
            ax += w0 * a0.x; ay += w0 * a0.y; az += w0 * a1.x; aw += w0 * a1.y;
        }
        ((float4*)O)[(size_t)n * 32 + lane] = make_float4(ax, ay, az, aw);
        float rx = ax, ry = ay, rz = az, rw = aw;
        if (relu_first) {
            rx = fmaxf(rx, 0.f); ry = fmaxf(ry, 0.f);
            rz = fmaxf(rz, 0.f); rw = fmaxf(rw, 0.f);
        }
        lsx += rx; lsy += ry; lsz += rz; lsw += rw;
        lqx += rx * rx; lqy += ry * ry; lqz += rz * rz; lqw += rw * rw;
    }
    float* ps = &ss[wid * 128 + lane * 4];
    float* pq = &sq[wid * 128 + lane * 4];
    ps[0] = lsx; ps[1] = lsy; ps[2] = lsz; ps[3] = lsw;
    pq[0] = lqx; pq[1] = lqy; pq[2] = lqz; pq[3] = lqw;
    __syncthreads();
    if (t < 128) {
        float a = 0.f, b = 0.f;
#pragma unroll
        for (int w = 0; w < 8; w++) {
            a += ss[w * 128 + t];
            b += sq[w * 128 + t];
        }
        atomicAdd(&stats[t], a);
        atomicAdd(&stats[128 + t], b);
    }
}

// ---------------- launch ----------------
extern "C" void kernel_launch(void* const* d_in, const int* in_sizes, int n_in,
                              void* d_out, int out_size) {
    const float *x = nullptr, *conv_w = nullptr, *conv_b = nullptr;
    const float *bn_g = nullptr, *bn_b = nullptr, *mlp_w = nullptr, *mlp_b = nullptr;
    const float *out_w = nullptr, *out_b = nullptr;
    const int* ei = nullptr;
    int n256 = 0;
    for (int i = 0; i < n_in; i++) {
        switch (in_sizes[i]) {
            case 6400000: x = (const float*)d_in[i]; break;
            case 1600000: ei = (const int*)d_in[i]; break;
            case 49152:   conv_w = (const float*)d_in[i]; break;
            case 384:     conv_b = (const float*)d_in[i]; break;
            case 32768:   mlp_w = (const float*)d_in[i]; break;
            case 128:     out_w = (const float*)d_in[i]; break;
            case 1:       out_b = (const float*)d_in[i]; break;
            case 256:
                if (n256 == 0) bn_g = (const float*)d_in[i];
                else if (n256 == 1) bn_b = (const float*)d_in[i];
                else mlp_b = (const float*)d_in[i];
                n256++;
                break;
            default: break;
        }
    }

    float *bufA, *bufB, *stats;
    __half* bufTh;
    u16 *whi, *wlo;
    cudaGetSymbolAddress((void**)&bufA, g_bufA);
    cudaGetSymbolAddress((void**)&bufB, g_bufB);
    cudaGetSymbolAddress((void**)&bufTh, g_bufTh);
    cudaGetSymbolAddress((void**)&whi, g_whi);
    cudaGetSymbolAddress((void**)&wlo, g_wlo);
    cudaGetSymbolAddress((void**)&stats, g_stats3);

    const int SMEM = 4 * IMG;  // 139264
    cudaFuncSetAttribute(k_gemm_mma, cudaFuncAttributeMaxDynamicSharedMemorySize, SMEM);

    const int GB = (NN + 127) / 128;  // 391
    const int EB = (EE + 255) / 256;

    // prep (weights + zero cnt/stats) + CSR build
    k_prep_w<<<(5 * 16384 + 255) / 256, 256>>>(conv_w, mlp_w);
    k_hist<<<EB, 256>>>(ei);
    k_scanA<<<SCAN_NT, 128>>>();
    k_scanB<<<1, 512>>>();
    k_scanC<<<SCAN_NT, 128>>>();
    k_fill<<<EB, 256>>>(ei);

    // layer 0
    k_gemm_mma<<<GB, 256, SMEM>>>(x, whi, wlo, nullptr, nullptr, bufTh, NN, 0, 0,
                                  nullptr, nullptr, nullptr, nullptr, nullptr, nullptr);
    k_gather<<<1184, 256>>>(bufTh, conv_b, bufB, stats, 0);

    // layer 1
    k_gemm_mma<<<GB, 256, SMEM>>>(bufB, whi + 16384, wlo + 16384, nullptr, nullptr, bufTh,
                                  NN, 0, 1, bn_g, bn_b, stats, nullptr, nullptr, nullptr);
    k_gather<<<1184, 256>>>(bufTh, conv_b + 128, bufB, stats + 256, 0);

    // layer 2
    k_gemm_mma<<<GB, 256, SMEM>>>(bufB, whi + 32768, wlo + 32768, nullptr, nullptr, bufTh,
                                  NN, 0, 1, bn_g + 128, bn_b + 128, stats + 256,
                                  nullptr, nullptr, nullptr);
    k_gather<<<1184, 256>>>(bufTh, conv_b + 256, bufB, stats + 512, 1);

    // mlp1: tmode 2 (bn1(relu(h2)) quirk), epi relu(+bias), fp32 out
    k_gemm_mma<<<GB, 256, SMEM>>>(bufB, whi + 49152, wlo + 49152, mlp_b, bufA, nullptr,
                                  NN, 1, 2, bn_g + 128, bn_b + 128, stats + 512,
                                  nullptr, nullptr, nullptr);
    // mlp2 + fused sigmoid head
    k_gemm_mma<<<GB, 256, SMEM>>>(bufA, whi + 65536, wlo + 65536, mlp_b + 128, nullptr, nullptr,
                                  NN, 2, 0, nullptr, nullptr, nullptr,
                                  out_w, out_b, (float*)d_out);
}

// round 9
// speedup vs baseline: 2.3905x; 1.0562x over previous
#include <cuda_runtime.h>
#include <cuda_bf16.h>
#include <cuda_fp16.h>
#include <math.h>

#define NN 50000
#define EE 800000
#define DD 128
#define BN_EPS 1e-5f
#define SCAN_NT ((NN + 127) / 128)   // 391

typedef unsigned long long u64;
typedef unsigned int u32;
typedef unsigned short u16;

// ---------------- scratch (no allocs allowed) ----------------
__device__ __half g_bufH[NN * DD];    // activations (gather out / gemm in)
__device__ __half g_bufTh[NN * DD];   // transformed messages (gemm out / gather in)
__device__ float  g_dis[NN];
__device__ float  g_stats3[3 * 256];
__device__ int    g_cnt[NN];
__device__ int    g_rowptr[NN];
__device__ int    g_cursor[NN];
__device__ int2   g_epack[EE];        // (src, bitcast(w))
__device__ int    g_tsum[512];
__device__ u16    g_whi[5 * 16384];
__device__ u16    g_wlo[5 * 16384];

// ---------------- mma helpers ----------------
__device__ __forceinline__ u32 su32(const void* p) {
    return (u32)__cvta_generic_to_shared(p);
}
__device__ __forceinline__ void ldsm_x4(u32& r0, u32& r1, u32& r2, u32& r3, u32 addr) {
    asm volatile("ldmatrix.sync.aligned.m8n8.x4.shared.b16 {%0,%1,%2,%3}, [%4];"
                 : "=r"(r0), "=r"(r1), "=r"(r2), "=r"(r3) : "r"(addr));
}
__device__ __forceinline__ void ldsm_x2(u32& r0, u32& r1, u32 addr) {
    asm volatile("ldmatrix.sync.aligned.m8n8.x2.shared.b16 {%0,%1}, [%2];"
                 : "=r"(r0), "=r"(r1) : "r"(addr));
}
__device__ __forceinline__ void mma16816(float* c, const u32* a, const u32* b) {
    asm volatile(
        "mma.sync.aligned.m16n8k16.row.col.f32.bf16.bf16.f32 "
        "{%0,%1,%2,%3}, {%4,%5,%6,%7}, {%8,%9}, {%0,%1,%2,%3};"
        : "+f"(c[0]), "+f"(c[1]), "+f"(c[2]), "+f"(c[3])
        : "r"(a[0]), "r"(a[1]), "r"(a[2]), "r"(a[3]), "r"(b[0]), "r"(b[1]));
}

// ---------------- weight prep (+ zero stats) ----------------
__global__ void k_prep_w(const float* __restrict__ conv_w, const float* __restrict__ mlp_w) {
    int idx = blockIdx.x * blockDim.x + threadIdx.x;
    if (idx < 3 * 256) g_stats3[idx] = 0.f;
    if (idx >= 5 * 16384) return;
    int w = idx >> 14;
    int r = idx & 16383;
    int fout = r >> 7;
    int k = r & 127;
    float v = (w < 3) ? conv_w[w * 16384 + k * 128 + fout]
                      : mlp_w[(w - 3) * 16384 + k * 128 + fout];
    __nv_bfloat16 hi = __float2bfloat16_rn(v);
    __nv_bfloat16 lo = __float2bfloat16_rn(v - __bfloat162float(hi));
    g_whi[idx] = __bfloat16_as_ushort(hi);   // [w][fout][k]
    g_wlo[idx] = __bfloat16_as_ushort(lo);
}

// ---------------- CSR build ----------------
__global__ void k_zero_cnt() {
    int i = blockIdx.x * blockDim.x + threadIdx.x;
    if (i < NN) g_cnt[i] = 0;
}
__global__ void k_hist(const int* __restrict__ ei) {
    int e = blockIdx.x * blockDim.x + threadIdx.x;
    if (e < EE) atomicAdd(&g_cnt[ei[EE + e]], 1);
}
// tile sums + deg norm
__global__ void k_scanA() {
    __shared__ int sh[4];
    int t = threadIdx.x;
    int i = blockIdx.x * 128 + t;
    int c = (i < NN) ? g_cnt[i] : 0;
    if (i < NN) g_dis[i] = rsqrtf((float)c + 1.0f);  // +1 self-loop
    int v = c;
#pragma unroll
    for (int o = 16; o; o >>= 1) v += __shfl_down_sync(0xFFFFFFFFu, v, o);
    if ((t & 31) == 0) sh[t >> 5] = v;
    __syncthreads();
    if (t == 0) g_tsum[blockIdx.x] = sh[0] + sh[1] + sh[2] + sh[3];
}
// per-tile scan + cross-tile base computed in-block (merged scanB)
__global__ void k_scanC() {
    __shared__ int sbase[128];
    __shared__ int sh[128];
    int t = threadIdx.x;
    int part = 0;
    for (int j = t; j < blockIdx.x; j += 128) part += g_tsum[j];
    sbase[t] = part;
    __syncthreads();
#pragma unroll
    for (int o = 64; o; o >>= 1) {
        if (t < o) sbase[t] += sbase[t + o];
        __syncthreads();
    }
    int base = sbase[0];
    int i = blockIdx.x * 128 + t;
    int v = (i < NN) ? g_cnt[i] : 0;
    sh[t] = v;
    __syncthreads();
    for (int o = 1; o < 128; o <<= 1) {
        int x = (t >= o) ? sh[t - o] : 0;
        __syncthreads();
        sh[t] += x;
        __syncthreads();
    }
    if (i < NN) {
        int ex = sh[t] - v + base;
        g_rowptr[i] = ex;
        g_cursor[i] = ex;
    }
}
__global__ void k_fill(const int* __restrict__ ei) {
    int e = blockIdx.x * blockDim.x + threadIdx.x;
    if (e >= EE) return;
    int src = ei[e];
    int dst = ei[EE + e];
    int pos = atomicAdd(&g_cursor[dst], 1);
    g_epack[pos] = make_int2(src, __float_as_int(g_dis[src] * g_dis[dst]));
}

// ---------------- tensor-core GEMM (bf16 3-split) ----------------
// input: X fp32 (if Xh==null) else Xh fp16
// omode: 0 = store fp16 raw; 1 = relu(.+bias) fp16; 2 = relu(.+bias) then fused sigmoid head
// tmode: 0 identity, 1 relu(bn(v)), 2 bn(relu(v))
#define PADK 136
#define IMG (128 * PADK * 2)
extern __shared__ char s_dyn[];
__global__ void __launch_bounds__(256, 1)
k_gemm_mma(const float* __restrict__ X, const __half* __restrict__ Xh,
           const u16* __restrict__ Wh, const u16* __restrict__ Wl,
           const float* __restrict__ bias, __half* __restrict__ Th,
           int n, int omode, int tmode,
           const float* __restrict__ gamma, const float* __restrict__ beta,
           const float* __restrict__ stats,
           const float* __restrict__ ow, const float* __restrict__ ob,
           float* __restrict__ dout) {
    __shared__ float s_scale[128], s_shift[128];
    __shared__ float s_part[128][4];
    char* sm = s_dyn;
    int t = threadIdx.x;
    int lane = t & 31, wid = t >> 5;
    int row0 = blockIdx.x * 128;

    if (tmode && t < 128) {
        float inv = 1.0f / (float)NN;
        float mean = stats[t] * inv;
        float var = stats[128 + t] * inv - mean * mean;
        float rs = rsqrtf(var + BN_EPS);
        float sc = rs * gamma[t];
        s_scale[t] = sc;
        s_shift[t] = beta[t] - mean * sc;
    }
    __syncthreads();

    // W images into padded smem
#pragma unroll
    for (int i = 0; i < 8; i++) {
        int idx = i * 256 + t;
        int row = idx >> 4, c8 = idx & 15;
        int off = row * PADK * 2 + c8 * 16;
        *(float4*)(sm + off) = ((const float4*)Wh)[idx];
        *(float4*)(sm + IMG + off) = ((const float4*)Wl)[idx];
    }

    // X tile -> transform -> bf16 hi/lo split
    if (Xh == nullptr) {
#pragma unroll
        for (int i = 0; i < 16; i++) {
            int idx = i * 256 + t;
            int row = idx >> 5;
            int c4 = idx & 31;
            int gr = row0 + row;
            float4 v = (gr < n) ? ((const float4*)X)[(size_t)gr * 32 + c4]
                                : make_float4(0.f, 0.f, 0.f, 0.f);
            float vv[4] = {v.x, v.y, v.z, v.w};
            u32 hw[2], lw[2];
#pragma unroll
            for (int j = 0; j < 2; j++) {
                __nv_bfloat16 h0 = __float2bfloat16_rn(vv[2 * j]);
                __nv_bfloat16 h1 = __float2bfloat16_rn(vv[2 * j + 1]);
                __nv_bfloat16 l0 = __float2bfloat16_rn(vv[2 * j] - __bfloat162float(h0));
                __nv_bfloat16 l1 = __float2bfloat16_rn(vv[2 * j + 1] - __bfloat162float(h1));
                hw[j] = ((u32)__bfloat16_as_ushort(h1) << 16) | __bfloat16_as_ushort(h0);
                lw[j] = ((u32)__bfloat16_as_ushort(l1) << 16) | __bfloat16_as_ushort(l0);
            }
            int off = row * PADK * 2 + c4 * 8;
            *(u32*)(sm + 2 * IMG + off) = hw[0];
            *(u32*)(sm + 2 * IMG + off + 4) = hw[1];
            *(u32*)(sm + 3 * IMG + off) = lw[0];
            *(u32*)(sm + 3 * IMG + off + 4) = lw[1];
        }
    } else {
#pragma unroll
        for (int i = 0; i < 8; i++) {
            int idx = i * 256 + t;       // uint4 index in [0,2048): 8 halves each
            int row = idx >> 4;
            int c8 = idx & 15;
            int gr = row0 + row;
            uint4 raw = make_uint4(0, 0, 0, 0);
            if (gr < n) raw = *(const uint4*)&Xh[(size_t)gr * 128 + c8 * 8];
            float f[8];
            float2 p;
            p = __half22float2(*(half2*)&raw.x); f[0] = p.x; f[1] = p.y;
            p = __half22float2(*(half2*)&raw.y); f[2] = p.x; f[3] = p.y;
            p = __half22float2(*(half2*)&raw.z); f[4] = p.x; f[5] = p.y;
            p = __half22float2(*(half2*)&raw.w); f[6] = p.x; f[7] = p.y;
            if (tmode) {
                int c0 = c8 * 8;
#pragma unroll
                for (int j = 0; j < 8; j++) {
                    float xv = f[j];
                    if (tmode == 2) xv = fmaxf(xv, 0.f);
                    float y = xv * s_scale[c0 + j] + s_shift[c0 + j];
                    if (tmode == 1) y = fmaxf(y, 0.f);
                    f[j] = y;
                }
            }
            u32 hw[4], lw[4];
#pragma unroll
            for (int j = 0; j < 4; j++) {
                __nv_bfloat16 h0 = __float2bfloat16_rn(f[2 * j]);
                __nv_bfloat16 h1 = __float2bfloat16_rn(f[2 * j + 1]);
                __nv_bfloat16 l0 = __float2bfloat16_rn(f[2 * j] - __bfloat162float(h0));
                __nv_bfloat16 l1 = __float2bfloat16_rn(f[2 * j + 1] - __bfloat162float(h1));
                hw[j] = ((u32)__bfloat16_as_ushort(h1) << 16) | __bfloat16_as_ushort(h0);
                lw[j] = ((u32)__bfloat16_as_ushort(l1) << 16) | __bfloat16_as_ushort(l0);
            }
            int off = row * PADK * 2 + c8 * 16;
            *(uint4*)(sm + 2 * IMG + off) = make_uint4(hw[0], hw[1], hw[2], hw[3]);
            *(uint4*)(sm + 3 * IMG + off) = make_uint4(lw[0], lw[1], lw[2], lw[3]);
        }
    }
    __syncthreads();

    int mw = wid >> 2, nw = wid & 3;
    float acc[4][4][4];
#pragma unroll
    for (int mt = 0; mt < 4; mt++)
#pragma unroll
        for (int nt = 0; nt < 4; nt++)
#pragma unroll
            for (int j = 0; j < 4; j++) acc[mt][nt][j] = 0.f;

    u32 sW_base[3], sA_base[3];
    sW_base[0] = su32(sm);       sA_base[0] = su32(sm + 2 * IMG);
    sW_base[1] = su32(sm + IMG); sA_base[1] = su32(sm + 2 * IMG);
    sW_base[2] = su32(sm);       sA_base[2] = su32(sm + 3 * IMG);

    int a_row = mw * 64 + (lane & 15);
    int a_coff = (lane >> 4) * 8;
    int b_row = nw * 32 + (lane & 7);
    int b_coff = ((lane >> 3) & 1) * 8;

#pragma unroll
    for (int p = 0; p < 3; p++) {
        u32 aB = sA_base[p], wB = sW_base[p];
#pragma unroll
        for (int ks = 0; ks < 8; ks++) {
            int kc = ks * 16;
            u32 a[4][4], b[4][2];
#pragma unroll
            for (int mt = 0; mt < 4; mt++)
                ldsm_x4(a[mt][0], a[mt][1], a[mt][2], a[mt][3],
                        aB + (u32)(((a_row + mt * 16) * PADK + kc + a_coff) * 2));
#pragma unroll
            for (int nt = 0; nt < 4; nt++)
                ldsm_x2(b[nt][0], b[nt][1],
                        wB + (u32)(((b_row + nt * 8) * PADK + kc + b_coff) * 2));
#pragma unroll
            for (int mt = 0; mt < 4; mt++)
#pragma unroll
                for (int nt = 0; nt < 4; nt++)
                    mma16816(acc[mt][nt], a[mt], b[nt]);
        }
    }

    // epilogue
    int g = lane >> 2, q = lane & 3;
#pragma unroll
    for (int mt = 0; mt < 4; mt++) {
        int rl1 = mw * 64 + mt * 16 + g;
        int r1 = row0 + rl1, r2 = r1 + 8;
        float p1 = 0.f, p2 = 0.f;
#pragma unroll
        for (int nt = 0; nt < 4; nt++) {
            int col = nw * 32 + nt * 8 + q * 2;
            float v0 = acc[mt][nt][0], v1 = acc[mt][nt][1];
            float v2 = acc[mt][nt][2], v3 = acc[mt][nt][3];
            if (omode >= 1) {   // bias + relu for BOTH mlp layers (incl. fused head)
                float2 bb = *(const float2*)&bias[col];
                v0 = fmaxf(v0 + bb.x, 0.f); v1 = fmaxf(v1 + bb.y, 0.f);
                v2 = fmaxf(v2 + bb.x, 0.f); v3 = fmaxf(v3 + bb.y, 0.f);
            }
            if (omode <= 1) {
                if (r1 < n) *(half2*)&Th[(size_t)r1 * 128 + col] = __floats2half2_rn(v0, v1);
                if (r2 < n) *(half2*)&Th[(size_t)r2 * 128 + col] = __floats2half2_rn(v2, v3);
            } else {
                float w0 = __ldg(&ow[col]), w1 = __ldg(&ow[col + 1]);
                p1 += v0 * w0 + v1 * w1;
                p2 += v2 * w0 + v3 * w1;
            }
        }
        if (omode == 2) {
            p1 += __shfl_down_sync(0xFFFFFFFFu, p1, 1, 4);
            p1 += __shfl_down_sync(0xFFFFFFFFu, p1, 2, 4);
            p2 += __shfl_down_sync(0xFFFFFFFFu, p2, 1, 4);
            p2 += __shfl_down_sync(0xFFFFFFFFu, p2, 2, 4);
            if (q == 0) {
                s_part[rl1][nw] = p1;
                s_part[rl1 + 8][nw] = p2;
            }
        }
    }
    if (omode == 2) {
        __syncthreads();
        if (t < 128) {
            int gr = row0 + t;
            if (gr < n) {
                float s = s_part[t][0] + s_part[t][1] + s_part[t][2] + s_part[t][3] + ob[0];
                dout[gr] = 1.0f / (1.0f + expf(-s));
            }
        }
    }
}

// ---------------- CSR gather (fp16 in/out, fp32 accumulate) + fused BN stats ----------------
__device__ __forceinline__ void acc_row(const __half* __restrict__ Th, int src, float w,
                                        int lane, float& ax, float& ay, float& az, float& aw) {
    uint2 u = *(const uint2*)&Th[(size_t)src * 128 + lane * 4];
    float2 a0 = __half22float2(*(half2*)&u.x);
    float2 a1 = __half22float2(*(half2*)&u.y);
    ax += w * a0.x; ay += w * a0.y; az += w * a1.x; aw += w * a1.y;
}

__global__ void k_gather(const __half* __restrict__ Th, const float* __restrict__ bias,
                         __half* __restrict__ O, float* __restrict__ stats, int relu_first) {
    __shared__ float ss[8 * 128];
    __shared__ float sq[8 * 128];
    int t = threadIdx.x;
    int lane = t & 31, wid = t >> 5;
    int gw = blockIdx.x * 8 + wid;
    int tot = gridDim.x * 8;
    float4 b4 = ((const float4*)bias)[lane];
    float lsx = 0, lsy = 0, lsz = 0, lsw = 0;
    float lqx = 0, lqy = 0, lqz = 0, lqw = 0;

    for (int n = gw; n < NN; n += tot) {
        float dn = g_dis[n];
        float sn = dn * dn;
        float ax = b4.x, ay = b4.y, az = b4.z, aw = b4.w;
        acc_row(Th, n, sn, lane, ax, ay, az, aw);
        int s = g_rowptr[n];
        int e = s + g_cnt[n];
        int i = s;
        for (; i + 3 < e; i += 4) {
            int2 p0 = __ldg(&g_epack[i]);
            int2 p1 = __ldg(&g_epack[i + 1]);
            int2 p2 = __ldg(&g_epack[i + 2]);
            int2 p3 = __ldg(&g_epack[i + 3]);
            acc_row(Th, p0.x, __int_as_float(p0.y), lane, ax, ay, az, aw);
            acc_row(Th, p1.x, __int_as_float(p1.y), lane, ax, ay, az, aw);
            acc_row(Th, p2.x, __int_as_float(p2.y), lane, ax, ay, az, aw);
            acc_row(Th, p3.x, __int_as_float(p3.y), lane, ax, ay, az, aw);
        }
        for (; i < e; i++) {
            int2 p0 = __ldg(&g_epack[i]);
            acc_row(Th, p0.x, __int_as_float(p0.y), lane, ax, ay, az, aw);
        }
        half2 o0 = __floats2half2_rn(ax, ay);
        half2 o1 = __floats2half2_rn(az, aw);
        uint2 ov;
        ov.x = *(u32*)&o0; ov.y = *(u32*)&o1;
        *(uint2*)&O[(size_t)n * 128 + lane * 4] = ov;
        float rx = ax, ry = ay, rz = az, rw = aw;
        if (relu_first) {
            rx = fmaxf(rx, 0.f); ry = fmaxf(ry, 0.f);
            rz = fmaxf(rz, 0.f); rw = fmaxf(rw, 0.f);
        }
        lsx += rx; lsy += ry; lsz += rz; lsw += rw;
        lqx += rx * rx; lqy += ry * ry; lqz += rz * rz; lqw += rw * rw;
    }
    float* ps = &ss[wid * 128 + lane * 4];
    float* pq = &sq[wid * 128 + lane * 4];
    ps[0] = lsx; ps[1] = lsy; ps[2] = lsz; ps[3] = lsw;
    pq[0] = lqx; pq[1] = lqy; pq[2] = lqz; pq[3] = lqw;
    __syncthreads();
    if (t < 128) {
        float a = 0.f, b = 0.f;
#pragma unroll
        for (int w = 0; w < 8; w++) {
            a += ss[w * 128 + t];
            b += sq[w * 128 + t];
        }
        atomicAdd(&stats[t], a);
        atomicAdd(&stats[128 + t], b);
    }
}

// ---------------- launch ----------------
extern "C" void kernel_launch(void* const* d_in, const int* in_sizes, int n_in,
                              void* d_out, int out_size) {
    const float *x = nullptr, *conv_w = nullptr, *conv_b = nullptr;
    const float *bn_g = nullptr, *bn_b = nullptr, *mlp_w = nullptr, *mlp_b = nullptr;
    const float *out_w = nullptr, *out_b = nullptr;
    const int* ei = nullptr;
    int n256 = 0;
    for (int i = 0; i < n_in; i++) {
        switch (in_sizes[i]) {
            case 6400000: x = (const float*)d_in[i]; break;
            case 1600000: ei = (const int*)d_in[i]; break;
            case 49152:   conv_w = (const float*)d_in[i]; break;
            case 384:     conv_b = (const float*)d_in[i]; break;
            case 32768:   mlp_w = (const float*)d_in[i]; break;
            case 128:     out_w = (const float*)d_in[i]; break;
            case 1:       out_b = (const float*)d_in[i]; break;
            case 256:
                if (n256 == 0) bn_g = (const float*)d_in[i];
                else if (n256 == 1) bn_b = (const float*)d_in[i];
                else mlp_b = (const float*)d_in[i];
                n256++;
                break;
            default: break;
        }
    }

    __half *bufH, *bufTh;
    float* stats;
    u16 *whi, *wlo;
    cudaGetSymbolAddress((void**)&bufH, g_bufH);
    cudaGetSymbolAddress((void**)&bufTh, g_bufTh);
    cudaGetSymbolAddress((void**)&whi, g_whi);
    cudaGetSymbolAddress((void**)&wlo, g_wlo);
    cudaGetSymbolAddress((void**)&stats, g_stats3);

    const int SMEM = 4 * IMG;  // 139264
    cudaFuncSetAttribute(k_gemm_mma, cudaFuncAttributeMaxDynamicSharedMemorySize, SMEM);

    const int GB = (NN + 127) / 128;  // 391
    const int NB = (NN + 255) / 256;
    const int EB = (EE + 255) / 256;

    // one-time side stream + events (created once; capture-safe fork/join)
    static cudaStream_t s1 = nullptr;
    static cudaEvent_t evRoot = nullptr, evJoin = nullptr;
    if (s1 == nullptr) {
        cudaStreamCreateWithFlags(&s1, cudaStreamNonBlocking);
        cudaEventCreateWithFlags(&evRoot, cudaEventDisableTiming);
        cudaEventCreateWithFlags(&evJoin, cudaEventDisableTiming);
    }

    // fork: CSR build on s1, weight prep + gemm0 on main stream
    cudaEventRecord(evRoot, 0);
    cudaStreamWaitEvent(s1, evRoot, 0);

    k_zero_cnt<<<NB, 256, 0, s1>>>();
    k_hist<<<EB, 256, 0, s1>>>(ei);
    k_scanA<<<SCAN_NT, 128, 0, s1>>>();
    k_scanC<<<SCAN_NT, 128, 0, s1>>>();
    k_fill<<<EB, 256, 0, s1>>>(ei);
    cudaEventRecord(evJoin, s1);

    k_prep_w<<<(5 * 16384 + 255) / 256, 256>>>(conv_w, mlp_w);
    k_gemm_mma<<<GB, 256, SMEM>>>(x, nullptr, whi, wlo, nullptr, bufTh, NN, 0, 0,
                                  nullptr, nullptr, nullptr, nullptr, nullptr, nullptr);

    cudaStreamWaitEvent(0, evJoin, 0);  // join before gather0

    // layer 0
    k_gather<<<1184, 256>>>(bufTh, conv_b, bufH, stats, 0);

    // layer 1
    k_gemm_mma<<<GB, 256, SMEM>>>(nullptr, bufH, whi + 16384, wlo + 16384, nullptr, bufTh,
                                  NN, 0, 1, bn_g, bn_b, stats, nullptr, nullptr, nullptr);
    k_gather<<<1184, 256>>>(bufTh, conv_b + 128, bufH, stats + 256, 0);

    // layer 2
    k_gemm_mma<<<GB, 256, SMEM>>>(nullptr, bufH, whi + 32768, wlo + 32768, nullptr, bufTh,
                                  NN, 0, 1, bn_g + 128, bn_b + 128, stats + 256,
                                  nullptr, nullptr, nullptr);
    k_gather<<<1184, 256>>>(bufTh, conv_b + 256, bufH, stats + 512, 1);

    // mlp1: tmode 2 (bn1(relu(h2)) quirk), relu(+bias) -> fp16 bufTh
    k_gemm_mma<<<GB, 256, SMEM>>>(nullptr, bufH, whi + 49152, wlo + 49152, mlp_b, bufTh,
                                  NN, 1, 2, bn_g + 128, bn_b + 128, stats + 512,
                                  nullptr, nullptr, nullptr);
    // mlp2 + fused sigmoid head (bias+relu now applied in omode==2 as well)
    k_gemm_mma<<<GB, 256, SMEM>>>(nullptr, bufTh, whi + 65536, wlo + 65536, mlp_b + 128, nullptr,
                                  NN, 2, 0, nullptr, nullptr, nullptr,
                                  out_w, out_b, (float*)d_out);
}

// round 10
// speedup vs baseline: 2.5608x; 1.0712x over previous
#include <cuda_runtime.h>
#include <cuda_bf16.h>
#include <cuda_fp16.h>
#include <math.h>

#define NN 50000
#define EE 800000
#define DD 128
#define BN_EPS 1e-5f
#define SCAN_NT ((NN + 127) / 128)   // 391

typedef unsigned long long u64;
typedef unsigned int u32;
typedef unsigned short u16;

// ---------------- scratch (no allocs allowed) ----------------
__device__ __half g_bufH[NN * DD];    // activations (gather out / gemm in)
__device__ __half g_bufTh[NN * DD];   // transformed messages (gemm out / gather in)
__device__ float  g_dis[NN];
__device__ float  g_stats3[3 * 256];
__device__ int    g_cnt[NN];
__device__ int    g_rowptr[NN];
__device__ int    g_cursor[NN];
__device__ int2   g_epack[EE];        // (src, bitcast(w))
__device__ int    g_tsum[512];
__device__ u16    g_whi[5 * 16384];
__device__ u16    g_wlo[5 * 16384];

// ---------------- mma helpers ----------------
__device__ __forceinline__ u32 su32(const void* p) {
    return (u32)__cvta_generic_to_shared(p);
}
__device__ __forceinline__ void ldsm_x4(u32& r0, u32& r1, u32& r2, u32& r3, u32 addr) {
    asm volatile("ldmatrix.sync.aligned.m8n8.x4.shared.b16 {%0,%1,%2,%3}, [%4];"
                 : "=r"(r0), "=r"(r1), "=r"(r2), "=r"(r3) : "r"(addr));
}
__device__ __forceinline__ void ldsm_x2(u32& r0, u32& r1, u32 addr) {
    asm volatile("ldmatrix.sync.aligned.m8n8.x2.shared.b16 {%0,%1}, [%2];"
                 : "=r"(r0), "=r"(r1) : "r"(addr));
}
__device__ __forceinline__ void mma16816(float* c, const u32* a, const u32* b) {
    asm volatile(
        "mma.sync.aligned.m16n8k16.row.col.f32.bf16.bf16.f32 "
        "{%0,%1,%2,%3}, {%4,%5,%6,%7}, {%8,%9}, {%0,%1,%2,%3};"
        : "+f"(c[0]), "+f"(c[1]), "+f"(c[2]), "+f"(c[3])
        : "r"(a[0]), "r"(a[1]), "r"(a[2]), "r"(a[3]), "r"(b[0]), "r"(b[1]));
}

// ---------------- weight prep (+ zero stats) ----------------
__global__ void k_prep_w(const float* __restrict__ conv_w, const float* __restrict__ mlp_w) {
    int idx = blockIdx.x * blockDim.x + threadIdx.x;
    if (idx < 3 * 256) g_stats3[idx] = 0.f;
    if (idx >= 5 * 16384) return;
    int w = idx >> 14;
    int r = idx & 16383;
    int fout = r >> 7;
    int k = r & 127;
    float v = (w < 3) ? conv_w[w * 16384 + k * 128 + fout]
                      : mlp_w[(w - 3) * 16384 + k * 128 + fout];
    __nv_bfloat16 hi = __float2bfloat16_rn(v);
    __nv_bfloat16 lo = __float2bfloat16_rn(v - __bfloat162float(hi));
    g_whi[idx] = __bfloat16_as_ushort(hi);   // [w][fout][k]
    g_wlo[idx] = __bfloat16_as_ushort(lo);
}

// ---------------- CSR build ----------------
__global__ void k_zero_cnt() {
    int i = blockIdx.x * blockDim.x + threadIdx.x;
    if (i < NN) g_cnt[i] = 0;
}
__global__ void k_hist(const int* __restrict__ ei) {
    int e = blockIdx.x * blockDim.x + threadIdx.x;
    if (e < EE) atomicAdd(&g_cnt[ei[EE + e]], 1);
}
// tile sums + deg norm
__global__ void k_scanA() {
    __shared__ int sh[4];
    int t = threadIdx.x;
    int i = blockIdx.x * 128 + t;
    int c = (i < NN) ? g_cnt[i] : 0;
    if (i < NN) g_dis[i] = rsqrtf((float)c + 1.0f);  // +1 self-loop
    int v = c;
#pragma unroll
    for (int o = 16; o; o >>= 1) v += __shfl_down_sync(0xFFFFFFFFu, v, o);
    if ((t & 31) == 0) sh[t >> 5] = v;
    __syncthreads();
    if (t == 0) g_tsum[blockIdx.x] = sh[0] + sh[1] + sh[2] + sh[3];
}
// per-tile scan + cross-tile base computed in-block (merged scanB)
__global__ void k_scanC() {
    __shared__ int sbase[128];
    __shared__ int sh[128];
    int t = threadIdx.x;
    int part = 0;
    for (int j = t; j < blockIdx.x; j += 128) part += g_tsum[j];
    sbase[t] = part;
    __syncthreads();
#pragma unroll
    for (int o = 64; o; o >>= 1) {
        if (t < o) sbase[t] += sbase[t + o];
        __syncthreads();
    }
    int base = sbase[0];
    int i = blockIdx.x * 128 + t;
    int v = (i < NN) ? g_cnt[i] : 0;
    sh[t] = v;
    __syncthreads();
    for (int o = 1; o < 128; o <<= 1) {
        int x = (t >= o) ? sh[t - o] : 0;
        __syncthreads();
        sh[t] += x;
        __syncthreads();
    }
    if (i < NN) {
        int ex = sh[t] - v + base;
        g_rowptr[i] = ex;
        g_cursor[i] = ex;
    }
}
__global__ void k_fill(const int* __restrict__ ei) {
    int e = blockIdx.x * blockDim.x + threadIdx.x;
    if (e >= EE) return;
    int src = ei[e];
    int dst = ei[EE + e];
    int pos = atomicAdd(&g_cursor[dst], 1);
    g_epack[pos] = make_int2(src, __float_as_int(g_dis[src] * g_dis[dst]));
}

// ---------------- tensor-core GEMM (bf16 3-split, 3-image smem, 2 CTA/SM) ----------------
// smem: S0 = Whi @0 ; S1 = Xhi @IMG ; S2 = Xlo (passes 1-2) then Wlo (pass 3) @2*IMG
// omode: 0 = store fp16 raw; 1 = relu(.+bias) fp16; 2 = relu(.+bias) + fused sigmoid head
// tmode: 0 identity, 1 relu(bn(v)), 2 bn(relu(v))
#define PADK 136
#define IMG (128 * PADK * 2)   // 34816
extern __shared__ char s_dyn[];

#define GEMM_PASS(aBase, wBase)                                                     \
    do {                                                                            \
        u32 aB = (aBase), wB = (wBase);                                             \
        _Pragma("unroll")                                                           \
        for (int ks = 0; ks < 8; ks++) {                                            \
            int kc = ks * 16;                                                       \
            u32 a[4][4], b[4][2];                                                   \
            _Pragma("unroll")                                                       \
            for (int mt = 0; mt < 4; mt++)                                          \
                ldsm_x4(a[mt][0], a[mt][1], a[mt][2], a[mt][3],                     \
                        aB + (u32)(((a_row + mt * 16) * PADK + kc + a_coff) * 2));  \
            _Pragma("unroll")                                                       \
            for (int nt = 0; nt < 4; nt++)                                          \
                ldsm_x2(b[nt][0], b[nt][1],                                         \
                        wB + (u32)(((b_row + nt * 8) * PADK + kc + b_coff) * 2));   \
            _Pragma("unroll")                                                       \
            for (int mt = 0; mt < 4; mt++)                                          \
                _Pragma("unroll")                                                   \
                for (int nt = 0; nt < 4; nt++)                                      \
                    mma16816(acc[mt][nt], a[mt], b[nt]);                            \
        }                                                                           \
    } while (0)

__global__ void __launch_bounds__(256, 2)
k_gemm_mma(const float* __restrict__ X, const __half* __restrict__ Xh,
           const u16* __restrict__ Wh, const u16* __restrict__ Wl,
           const float* __restrict__ bias, __half* __restrict__ Th,
           int n, int omode, int tmode,
           const float* __restrict__ gamma, const float* __restrict__ beta,
           const float* __restrict__ stats,
           const float* __restrict__ ow, const float* __restrict__ ob,
           float* __restrict__ dout) {
    __shared__ float s_scale[128], s_shift[128];
    __shared__ float s_part[128][4];
    char* sm = s_dyn;
    int t = threadIdx.x;
    int lane = t & 31, wid = t >> 5;
    int row0 = blockIdx.x * 128;

    if (tmode && t < 128) {
        float inv = 1.0f / (float)NN;
        float mean = stats[t] * inv;
        float var = stats[128 + t] * inv - mean * mean;
        float rs = rsqrtf(var + BN_EPS);
        float sc = rs * gamma[t];
        s_scale[t] = sc;
        s_shift[t] = beta[t] - mean * sc;
    }
    __syncthreads();

    // Whi image into S0
#pragma unroll
    for (int i = 0; i < 8; i++) {
        int idx = i * 256 + t;
        int row = idx >> 4, c8 = idx & 15;
        *(float4*)(sm + row * PADK * 2 + c8 * 16) = ((const float4*)Wh)[idx];
    }

    // X tile -> transform -> bf16 hi (S1) / lo (S2)
    if (Xh == nullptr) {
#pragma unroll
        for (int i = 0; i < 16; i++) {
            int idx = i * 256 + t;
            int row = idx >> 5;
            int c4 = idx & 31;
            int gr = row0 + row;
            float4 v = (gr < n) ? ((const float4*)X)[(size_t)gr * 32 + c4]
                                : make_float4(0.f, 0.f, 0.f, 0.f);
            float vv[4] = {v.x, v.y, v.z, v.w};
            u32 hw[2], lw[2];
#pragma unroll
            for (int j = 0; j < 2; j++) {
                __nv_bfloat16 h0 = __float2bfloat16_rn(vv[2 * j]);
                __nv_bfloat16 h1 = __float2bfloat16_rn(vv[2 * j + 1]);
                __nv_bfloat16 l0 = __float2bfloat16_rn(vv[2 * j] - __bfloat162float(h0));
                __nv_bfloat16 l1 = __float2bfloat16_rn(vv[2 * j + 1] - __bfloat162float(h1));
                hw[j] = ((u32)__bfloat16_as_ushort(h1) << 16) | __bfloat16_as_ushort(h0);
                lw[j] = ((u32)__bfloat16_as_ushort(l1) << 16) | __bfloat16_as_ushort(l0);
            }
            int off = row * PADK * 2 + c4 * 8;
            *(u32*)(sm + IMG + off) = hw[0];
            *(u32*)(sm + IMG + off + 4) = hw[1];
            *(u32*)(sm + 2 * IMG + off) = lw[0];
            *(u32*)(sm + 2 * IMG + off + 4) = lw[1];
        }
    } else {
#pragma unroll
        for (int i = 0; i < 8; i++) {
            int idx = i * 256 + t;       // uint4 index: 8 halves each
            int row = idx >> 4;
            int c8 = idx & 15;
            int gr = row0 + row;
            uint4 raw = make_uint4(0, 0, 0, 0);
            if (gr < n) raw = *(const uint4*)&Xh[(size_t)gr * 128 + c8 * 8];
            float f[8];
            float2 p;
            p = __half22float2(*(half2*)&raw.x); f[0] = p.x; f[1] = p.y;
            p = __half22float2(*(half2*)&raw.y); f[2] = p.x; f[3] = p.y;
            p = __half22float2(*(half2*)&raw.z); f[4] = p.x; f[5] = p.y;
            p = __half22float2(*(half2*)&raw.w); f[6] = p.x; f[7] = p.y;
            if (tmode) {
                int c0 = c8 * 8;
#pragma unroll
                for (int j = 0; j < 8; j++) {
                    float xv = f[j];
                    if (tmode == 2) xv = fmaxf(xv, 0.f);
                    float y = xv * s_scale[c0 + j] + s_shift[c0 + j];
                    if (tmode == 1) y = fmaxf(y, 0.f);
                    f[j] = y;
                }
            }
            u32 hw[4], lw[4];
#pragma unroll
            for (int j = 0; j < 4; j++) {
                __nv_bfloat16 h0 = __float2bfloat16_rn(f[2 * j]);
                __nv_bfloat16 h1 = __float2bfloat16_rn(f[2 * j + 1]);
                __nv_bfloat16 l0 = __float2bfloat16_rn(f[2 * j] - __bfloat162float(h0));
                __nv_bfloat16 l1 = __float2bfloat16_rn(f[2 * j + 1] - __bfloat162float(h1));
                hw[j] = ((u32)__bfloat16_as_ushort(h1) << 16) | __bfloat16_as_ushort(h0);
                lw[j] = ((u32)__bfloat16_as_ushort(l1) << 16) | __bfloat16_as_ushort(l0);
            }
            int off = row * PADK * 2 + c8 * 16;
            *(uint4*)(sm + IMG + off) = make_uint4(hw[0], hw[1], hw[2], hw[3]);
            *(uint4*)(sm + 2 * IMG + off) = make_uint4(lw[0], lw[1], lw[2], lw[3]);
        }
    }
    __syncthreads();

    int mw = wid >> 2, nw = wid & 3;
    float acc[4][4][4];
#pragma unroll
    for (int mt = 0; mt < 4; mt++)
#pragma unroll
        for (int nt = 0; nt < 4; nt++)
#pragma unroll
            for (int j = 0; j < 4; j++) acc[mt][nt][j] = 0.f;

    int a_row = mw * 64 + (lane & 15);
    int a_coff = (lane >> 4) * 8;
    int b_row = nw * 32 + (lane & 7);
    int b_coff = ((lane >> 3) & 1) * 8;

    u32 sS0 = su32(sm), sS1 = su32(sm + IMG), sS2 = su32(sm + 2 * IMG);

    GEMM_PASS(sS1, sS0);   // Xhi * Whi
    GEMM_PASS(sS2, sS0);   // Xlo * Whi
    __syncthreads();
    // overwrite S2 (Xlo, now dead) with Wlo
#pragma unroll
    for (int i = 0; i < 8; i++) {
        int idx = i * 256 + t;
        int row = idx >> 4, c8 = idx & 15;
        *(float4*)(sm + 2 * IMG + row * PADK * 2 + c8 * 16) = ((const float4*)Wl)[idx];
    }
    __syncthreads();
    GEMM_PASS(sS1, sS2);   // Xhi * Wlo

    // epilogue
    int g = lane >> 2, q = lane & 3;
#pragma unroll
    for (int mt = 0; mt < 4; mt++) {
        int rl1 = mw * 64 + mt * 16 + g;
        int r1 = row0 + rl1, r2 = r1 + 8;
        float p1 = 0.f, p2 = 0.f;
#pragma unroll
        for (int nt = 0; nt < 4; nt++) {
            int col = nw * 32 + nt * 8 + q * 2;
            float v0 = acc[mt][nt][0], v1 = acc[mt][nt][1];
            float v2 = acc[mt][nt][2], v3 = acc[mt][nt][3];
            if (omode >= 1) {   // bias + relu for both mlp layers (incl. fused head)
                float2 bb = *(const float2*)&bias[col];
                v0 = fmaxf(v0 + bb.x, 0.f); v1 = fmaxf(v1 + bb.y, 0.f);
                v2 = fmaxf(v2 + bb.x, 0.f); v3 = fmaxf(v3 + bb.y, 0.f);
            }
            if (omode <= 1) {
                if (r1 < n) *(half2*)&Th[(size_t)r1 * 128 + col] = __floats2half2_rn(v0, v1);
                if (r2 < n) *(half2*)&Th[(size_t)r2 * 128 + col] = __floats2half2_rn(v2, v3);
            } else {
                float w0 = __ldg(&ow[col]), w1 = __ldg(&ow[col + 1]);
                p1 += v0 * w0 + v1 * w1;
                p2 += v2 * w0 + v3 * w1;
            }
        }
        if (omode == 2) {
            p1 += __shfl_down_sync(0xFFFFFFFFu, p1, 1, 4);
            p1 += __shfl_down_sync(0xFFFFFFFFu, p1, 2, 4);
            p2 += __shfl_down_sync(0xFFFFFFFFu, p2, 1, 4);
            p2 += __shfl_down_sync(0xFFFFFFFFu, p2, 2, 4);
            if (q == 0) {
                s_part[rl1][nw] = p1;
                s_part[rl1 + 8][nw] = p2;
            }
        }
    }
    if (omode == 2) {
        __syncthreads();
        if (t < 128) {
            int gr = row0 + t;
            if (gr < n) {
                float s = s_part[t][0] + s_part[t][1] + s_part[t][2] + s_part[t][3] + ob[0];
                dout[gr] = 1.0f / (1.0f + expf(-s));
            }
        }
    }
}

// ---------------- CSR gather (fp16, dual-node interleaved) + fused BN stats ----------------
__device__ __forceinline__ void acc_row4(const __half* __restrict__ Th, int src, float w,
                                         int lane, float* A) {
    uint2 u = *(const uint2*)&Th[(size_t)src * 128 + lane * 4];
    float2 a0 = __half22float2(*(half2*)&u.x);
    float2 a1 = __half22float2(*(half2*)&u.y);
    A[0] += w * a0.x; A[1] += w * a0.y; A[2] += w * a1.x; A[3] += w * a1.y;
}

__global__ void k_gather(const __half* __restrict__ Th, const float* __restrict__ bias,
                         __half* __restrict__ O, float* __restrict__ stats, int relu_first) {
    __shared__ float ss[8 * 128];
    __shared__ float sq[8 * 128];
    int t = threadIdx.x;
    int lane = t & 31, wid = t >> 5;
    int gw = blockIdx.x * 8 + wid;
    int tot = gridDim.x * 8;
    float4 b4 = ((const float4*)bias)[lane];
    float ls[4] = {0, 0, 0, 0};
    float lq[4] = {0, 0, 0, 0};

    for (int n1 = gw; n1 < NN; n1 += 2 * tot) {
        int n2 = n1 + tot;
        bool h2 = n2 < NN;
        float A[4] = {b4.x, b4.y, b4.z, b4.w};
        float B[4] = {b4.x, b4.y, b4.z, b4.w};
        float d1 = g_dis[n1];
        acc_row4(Th, n1, d1 * d1, lane, A);
        int i1 = g_rowptr[n1], e1 = i1 + g_cnt[n1];
        int i2 = 0, e2 = 0;
        if (h2) {
            float d2 = g_dis[n2];
            acc_row4(Th, n2, d2 * d2, lane, B);
            i2 = g_rowptr[n2];
            e2 = i2 + g_cnt[n2];
        }
        // interleaved 2+2: two independent dependency chains
        while (i1 + 1 < e1 && i2 + 1 < e2) {
            int2 pa = __ldg(&g_epack[i1]);
            int2 pb = __ldg(&g_epack[i1 + 1]);
            int2 pc = __ldg(&g_epack[i2]);
            int2 pd = __ldg(&g_epack[i2 + 1]);
            acc_row4(Th, pa.x, __int_as_float(pa.y), lane, A);
            acc_row4(Th, pc.x, __int_as_float(pc.y), lane, B);
            acc_row4(Th, pb.x, __int_as_float(pb.y), lane, A);
            acc_row4(Th, pd.x, __int_as_float(pd.y), lane, B);
            i1 += 2;
            i2 += 2;
        }
        for (; i1 + 3 < e1; i1 += 4) {
            int2 p0 = __ldg(&g_epack[i1]);
            int2 p1 = __ldg(&g_epack[i1 + 1]);
            int2 p2 = __ldg(&g_epack[i1 + 2]);
            int2 p3 = __ldg(&g_epack[i1 + 3]);
            acc_row4(Th, p0.x, __int_as_float(p0.y), lane, A);
            acc_row4(Th, p1.x, __int_as_float(p1.y), lane, A);
            acc_row4(Th, p2.x, __int_as_float(p2.y), lane, A);
            acc_row4(Th, p3.x, __int_as_float(p3.y), lane, A);
        }
        for (; i1 < e1; i1++) {
            int2 p0 = __ldg(&g_epack[i1]);
            acc_row4(Th, p0.x, __int_as_float(p0.y), lane, A);
        }
        for (; i2 + 3 < e2; i2 += 4) {
            int2 p0 = __ldg(&g_epack[i2]);
            int2 p1 = __ldg(&g_epack[i2 + 1]);
            int2 p2 = __ldg(&g_epack[i2 + 2]);
            int2 p3 = __ldg(&g_epack[i2 + 3]);
            acc_row4(Th, p0.x, __int_as_float(p0.y), lane, B);
            acc_row4(Th, p1.x, __int_as_float(p1.y), lane, B);
            acc_row4(Th, p2.x, __int_as_float(p2.y), lane, B);
            acc_row4(Th, p3.x, __int_as_float(p3.y), lane, B);
        }
        for (; i2 < e2; i2++) {
            int2 p0 = __ldg(&g_epack[i2]);
            acc_row4(Th, p0.x, __int_as_float(p0.y), lane, B);
        }
        // store + stats
        {
            half2 o0 = __floats2half2_rn(A[0], A[1]);
            half2 o1 = __floats2half2_rn(A[2], A[3]);
            uint2 ov;
            ov.x = *(u32*)&o0; ov.y = *(u32*)&o1;
            *(uint2*)&O[(size_t)n1 * 128 + lane * 4] = ov;
#pragma unroll
            for (int j = 0; j < 4; j++) {
                float r = relu_first ? fmaxf(A[j], 0.f) : A[j];
                ls[j] += r;
                lq[j] += r * r;
            }
        }
        if (h2) {
            half2 o0 = __floats2half2_rn(B[0], B[1]);
            half2 o1 = __floats2half2_rn(B[2], B[3]);
            uint2 ov;
            ov.x = *(u32*)&o0; ov.y = *(u32*)&o1;
            *(uint2*)&O[(size_t)n2 * 128 + lane * 4] = ov;
#pragma unroll
            for (int j = 0; j < 4; j++) {
                float r = relu_first ? fmaxf(B[j], 0.f) : B[j];
                ls[j] += r;
                lq[j] += r * r;
            }
        }
    }
    float* ps = &ss[wid * 128 + lane * 4];
    float* pq = &sq[wid * 128 + lane * 4];
#pragma unroll
    for (int j = 0; j < 4; j++) {
        ps[j] = ls[j];
        pq[j] = lq[j];
    }
    __syncthreads();
    if (t < 128) {
        float a = 0.f, b = 0.f;
#pragma unroll
        for (int w = 0; w < 8; w++) {
            a += ss[w * 128 + t];
            b += sq[w * 128 + t];
        }
        atomicAdd(&stats[t], a);
        atomicAdd(&stats[128 + t], b);
    }
}

// ---------------- launch ----------------
extern "C" void kernel_launch(void* const* d_in, const int* in_sizes, int n_in,
                              void* d_out, int out_size) {
    const float *x = nullptr, *conv_w = nullptr, *conv_b = nullptr;
    const float *bn_g = nullptr, *bn_b = nullptr, *mlp_w = nullptr, *mlp_b = nullptr;
    const float *out_w = nullptr, *out_b = nullptr;
    const int* ei = nullptr;
    int n256 = 0;
    for (int i = 0; i < n_in; i++) {
        switch (in_sizes[i]) {
            case 6400000: x = (const float*)d_in[i]; break;
            case 1600000: ei = (const int*)d_in[i]; break;
            case 49152:   conv_w = (const float*)d_in[i]; break;
            case 384:     conv_b = (const float*)d_in[i]; break;
            case 32768:   mlp_w = (const float*)d_in[i]; break;
            case 128:     out_w = (const float*)d_in[i]; break;
            case 1:       out_b = (const float*)d_in[i]; break;
            case 256:
                if (n256 == 0) bn_g = (const float*)d_in[i];
                else if (n256 == 1) bn_b = (const float*)d_in[i];
                else mlp_b = (const float*)d_in[i];
                n256++;
                break;
            default: break;
        }
    }

    __half *bufH, *bufTh;
    float* stats;
    u16 *whi, *wlo;
    cudaGetSymbolAddress((void**)&bufH, g_bufH);
    cudaGetSymbolAddress((void**)&bufTh, g_bufTh);
    cudaGetSymbolAddress((void**)&whi, g_whi);
    cudaGetSymbolAddress((void**)&wlo, g_wlo);
    cudaGetSymbolAddress((void**)&stats, g_stats3);

    const int SMEM = 3 * IMG;  // 104448 -> 2 CTAs/SM
    cudaFuncSetAttribute(k_gemm_mma, cudaFuncAttributeMaxDynamicSharedMemorySize, SMEM);

    const int GB = (NN + 127) / 128;  // 391
    const int NB = (NN + 255) / 256;
    const int EB = (EE + 255) / 256;

    // one-time side stream + events (created once; capture-safe fork/join)
    static cudaStream_t s1 = nullptr;
    static cudaEvent_t evRoot = nullptr, evJoin = nullptr;
    if (s1 == nullptr) {
        cudaStreamCreateWithFlags(&s1, cudaStreamNonBlocking);
        cudaEventCreateWithFlags(&evRoot, cudaEventDisableTiming);
        cudaEventCreateWithFlags(&evJoin, cudaEventDisableTiming);
    }

    // fork: CSR build on s1, weight prep + gemm0 on main stream
    cudaEventRecord(evRoot, 0);
    cudaStreamWaitEvent(s1, evRoot, 0);

    k_zero_cnt<<<NB, 256, 0, s1>>>();
    k_hist<<<EB, 256, 0, s1>>>(ei);
    k_scanA<<<SCAN_NT, 128, 0, s1>>>();
    k_scanC<<<SCAN_NT, 128, 0, s1>>>();
    k_fill<<<EB, 256, 0, s1>>>(ei);
    cudaEventRecord(evJoin, s1);

    k_prep_w<<<(5 * 16384 + 255) / 256, 256>>>(conv_w, mlp_w);
    k_gemm_mma<<<GB, 256, SMEM>>>(x, nullptr, whi, wlo, nullptr, bufTh, NN, 0, 0,
                                  nullptr, nullptr, nullptr, nullptr, nullptr, nullptr);

    cudaStreamWaitEvent(0, evJoin, 0);  // join before gather0

    // layer 0
    k_gather<<<1184, 256>>>(bufTh, conv_b, bufH, stats, 0);

    // layer 1
    k_gemm_mma<<<GB, 256, SMEM>>>(nullptr, bufH, whi + 16384, wlo + 16384, nullptr, bufTh,
                                  NN, 0, 1, bn_g, bn_b, stats, nullptr, nullptr, nullptr);
    k_gather<<<1184, 256>>>(bufTh, conv_b + 128, bufH, stats + 256, 0);

    // layer 2
    k_gemm_mma<<<GB, 256, SMEM>>>(nullptr, bufH, whi + 32768, wlo + 32768, nullptr, bufTh,
                                  NN, 0, 1, bn_g + 128, bn_b + 128, stats + 256,
                                  nullptr, nullptr, nullptr);
    k_gather<<<1184, 256>>>(bufTh, conv_b + 256, bufH, stats + 512, 1);

    // mlp1: tmode 2 (bn1(relu(h2)) quirk), relu(+bias) -> fp16 bufTh
    k_gemm_mma<<<GB, 256, SMEM>>>(nullptr, bufH, whi + 49152, wlo + 49152, mlp_b, bufTh,
                                  NN, 1, 2, bn_g + 128, bn_b + 128, stats + 512,
                                  nullptr, nullptr, nullptr);
    // mlp2 + fused sigmoid head
    k_gemm_mma<<<GB, 256, SMEM>>>(nullptr, bufTh, whi + 65536, wlo + 65536, mlp_b + 128, nullptr,
                                  NN, 2, 0, nullptr, nullptr, nullptr,
                                  out_w, out_b, (float*)d_out);
}